// round 14
// baseline (speedup 1.0000x reference)
#include <cuda_runtime.h>
#include <cstdint>
#include <cstddef>

// ---------------------------------------------------------------------------
// Problem constants
// ---------------------------------------------------------------------------
constexpr int B    = 4;
constexpr int CIN  = 128;
constexpr int NPT  = 1024;   // points
constexpr int KNN  = 9;
constexpr int MPT  = 4096;   // upsampled points = 4*N
constexpr int NCAND = 24;    // fp32 candidate shortlist size
constexpr float EPS_BN = 1e-5f;

// ---------------------------------------------------------------------------
// f32x2 packed-FMA helpers
// ---------------------------------------------------------------------------
using u64 = unsigned long long;
__device__ __forceinline__ u64 dup2(float v) {
    u64 r; asm("mov.b64 %0, {%1, %1};" : "=l"(r) : "f"(v)); return r;
}
__device__ __forceinline__ u64 pack2(float a, float b) {
    u64 r; asm("mov.b64 %0, {%1, %2};" : "=l"(r) : "f"(a), "f"(b)); return r;
}
__device__ __forceinline__ u64 fma2(u64 a, u64 b, u64 c) {
    u64 d; asm("fma.rn.f32x2 %0, %1, %2, %3;" : "=l"(d) : "l"(a), "l"(b), "l"(c)); return d;
}
__device__ __forceinline__ void unpack2(u64 v, float& lo, float& hi) {
    asm("mov.b64 {%0, %1}, %2;" : "=f"(lo), "=f"(hi) : "l"(v));
}

// ---------------------------------------------------------------------------
// Scratch buffer offsets (floats)
// ---------------------------------------------------------------------------
constexpr size_t SZ_XN   = (size_t)B*CIN*NPT;
constexpr size_t SZ_SQ   = (size_t)B*NPT;
constexpr size_t SZ_DOT  = (size_t)B*NPT*NPT;
constexpr size_t SZ_U    = (size_t)B*512*NPT;
constexpr size_t SZ_UV   = (size_t)B*256*NPT;
constexpr size_t SZ_PART = 256*64*2;
constexpr size_t SZ_NET  = (size_t)B*130*MPT;
constexpr size_t SZ_PFG  = (size_t)B*64*MPT;
constexpr size_t SZ_ROW  = (size_t)B*MPT;
constexpr size_t SZ_Y1   = (size_t)B*256*MPT;

constexpr size_t O_XN    = 0;
constexpr size_t O_XNT   = O_XN   + SZ_XN;
constexpr size_t O_XTR   = O_XNT  + SZ_XN;
constexpr size_t O_SQ    = O_XTR  + SZ_XN;
constexpr size_t O_DOT   = O_SQ   + SZ_SQ;
constexpr size_t O_W1AB  = O_DOT  + SZ_DOT;            // [512][128]
constexpr size_t O_W2A   = O_W1AB + 512*128;
constexpr size_t O_W2B   = O_W2A  + 256*128;
constexpr size_t O_WFG   = O_W2B  + 256*128;           // [64][130]
constexpr size_t O_U     = O_WFG  + 64*130;            // [B][512][NPT]
constexpr size_t O_MXA   = O_U    + SZ_U;
constexpr size_t O_MXB   = O_MXA  + SZ_UV;
constexpr size_t O_PARTA = O_MXB  + SZ_UV;
constexpr size_t O_PARTB = O_PARTA+ SZ_PART;
constexpr size_t O_AA    = O_PARTB+ SZ_PART;
constexpr size_t O_CA    = O_AA   + 256;
constexpr size_t O_AB2   = O_CA   + 256;
constexpr size_t O_CB2   = O_AB2  + 256;
constexpr size_t O_NET   = O_CB2  + 256;
constexpr size_t O_PFG   = O_NET  + SZ_NET;            // [B][64][MPT]
constexpr size_t O_PH    = O_PFG  + SZ_PFG;            // [B][130][MPT]
constexpr size_t O_FG    = O_PH   + SZ_NET;            // [B][64][MPT]
constexpr size_t O_HN    = O_FG   + SZ_PFG;            // [B][130][MPT]
constexpr size_t O_SCFG  = O_HN   + SZ_NET;
constexpr size_t O_BIFG  = O_SCFG + 64;
constexpr size_t O_SCH   = O_BIFG + 64;
constexpr size_t O_BIH   = O_SCH  + 130;
constexpr size_t O_RMAX  = O_BIH  + 130;
constexpr size_t O_RINV  = O_RMAX + SZ_ROW;
constexpr size_t O_NET2  = O_RINV + SZ_ROW;
constexpr size_t O_Y1    = O_NET2 + SZ_NET;
constexpr size_t O_END   = O_Y1   + SZ_Y1;

__device__ float  g_buf[O_END];
__device__ int    g_ibuf[(size_t)B*NPT*18];
__device__ int    g_cand[(size_t)B*NPT*NCAND];
__device__ double g_dbuf[(size_t)B*NPT*CIN + (size_t)B*NPT];

// ---------------------------------------------------------------------------
// 0. Weight prep: W1AB=[Wa1;Wb1] (512x128), W2A/W2B (256x128), WFG=[Wf;Wg]
// ---------------------------------------------------------------------------
__global__ void prep_w_kernel(const float* __restrict__ Wa, const float* __restrict__ Wb,
                              const float* __restrict__ Wf, const float* __restrict__ Wg,
                              float* W1AB, float* W2A, float* W2B, float* WFG) {
    int idx = blockIdx.x * 256 + threadIdx.x;
    if (idx < 65536) {
        int o = idx >> 7, c = idx & 127;
        W1AB[idx] = (o < 256) ? Wa[o*256 + c] : Wb[(o-256)*256 + c];
    } else if (idx < 98304) {
        int j = idx - 65536; int o = j >> 7, c = j & 127;
        W2A[j] = Wa[o*256 + 128 + c];
    } else if (idx < 131072) {
        int j = idx - 98304; int o = j >> 7, c = j & 127;
        W2B[j] = Wb[o*256 + 128 + c];
    } else if (idx < 131072 + 64*130) {
        int j = idx - 131072;
        WFG[j] = (j < 32*130) ? Wf[j] : Wg[j - 32*130];
    }
}

// ---------------------------------------------------------------------------
// 1. Normalize in DOUBLE, warp-per-point
// ---------------------------------------------------------------------------
__global__ __launch_bounds__(256)
void normalize_kernel(const float* __restrict__ x,
                      float* __restrict__ xn, float* __restrict__ xnT,
                      float* __restrict__ xTr, float* __restrict__ sq,
                      double* __restrict__ xnd, double* __restrict__ sqd) {
    int gw = (blockIdx.x * 256 + threadIdx.x) >> 5;
    if (gw >= B * NPT) return;
    int lane = threadIdx.x & 31;
    int b = gw >> 10, n = gw & 1023;
    const float* xp = x + (size_t)b * CIN * NPT + n;
    float vf[4];
    double ss = 0.0;
    #pragma unroll
    for (int i = 0; i < 4; i++) {
        float v = xp[(size_t)(i*32 + lane) * NPT];
        vf[i] = v;
        ss += (double)v * (double)v;
    }
    #pragma unroll
    for (int off = 16; off > 0; off >>= 1)
        ss += __shfl_xor_sync(0xffffffffu, ss, off);
    double nrm = sqrt(ss); if (nrm < 1e-12) nrm = 1e-12;
    double inv = 1.0 / nrm;
    double s2 = 0.0;
    #pragma unroll
    for (int i = 0; i < 4; i++) {
        int c = i*32 + lane;
        double v = (double)vf[i] * inv;
        xn[((size_t)b*CIN + c) * NPT + n] = (float)v;
        xnT[((size_t)b*NPT + n) * CIN + c] = (float)v;
        xTr[((size_t)b*NPT + n) * CIN + c] = vf[i];
        xnd[((size_t)b*NPT + n) * CIN + c] = v;
        s2 += v * v;
    }
    #pragma unroll
    for (int off = 16; off > 0; off >>= 1)
        s2 += __shfl_xor_sync(0xffffffffu, s2, off);
    if (lane == 0) { sq[gw] = (float)s2; sqd[gw] = s2; }
}

// ---------------------------------------------------------------------------
// 2. Tiled GEMM v2: 64x64 block, 4m x 4n per thread
// ---------------------------------------------------------------------------
__global__ __launch_bounds__(256)
void gemm_kernel(const float* __restrict__ A, size_t aStride,
                 const float* __restrict__ X, const float* __restrict__ bias,
                 float* __restrict__ C, int M, int K, int Nn, int doRelu) {
    __shared__ float As[32][68];   // [k][m]
    __shared__ float Xs[32][68];   // [k][n]
    int b = blockIdx.z;
    const float* Ab = A + (size_t)b * aStride;
    const float* Xb = X + (size_t)b * K * Nn;
    float* Cb = C + (size_t)b * M * Nn;
    int m0 = blockIdx.y * 64, n0 = blockIdx.x * 64;
    int tid = threadIdx.x;
    int tn = tid & 15, tm = tid >> 4;
    u64 acc[4][2] = {};
    int kTiles = (K + 31) / 32;
    for (int kt = 0; kt < kTiles; kt++) {
        int k0 = kt * 32;
        for (int i = tid; i < 64*32; i += 256) {
            int m = i >> 5, k = i & 31;
            float v = 0.f;
            if (m0 + m < M && k0 + k < K) v = Ab[(size_t)(m0+m)*K + k0 + k];
            As[k][m] = v;
        }
        for (int i = tid; i < 32*64; i += 256) {
            int k = i >> 6, n = i & 63;
            float v = 0.f;
            if (k0 + k < K) v = Xb[(size_t)(k0+k)*Nn + n0 + n];
            Xs[k][n] = v;
        }
        __syncthreads();
        #pragma unroll
        for (int kk = 0; kk < 32; kk++) {
            float4 a4 = *reinterpret_cast<const float4*>(&As[kk][tm*4]);
            u64 x0 = *reinterpret_cast<const u64*>(&Xs[kk][tn*4]);
            u64 x1 = *reinterpret_cast<const u64*>(&Xs[kk][tn*4 + 2]);
            u64 a0 = dup2(a4.x), a1 = dup2(a4.y), a2 = dup2(a4.z), a3 = dup2(a4.w);
            acc[0][0] = fma2(a0, x0, acc[0][0]); acc[0][1] = fma2(a0, x1, acc[0][1]);
            acc[1][0] = fma2(a1, x0, acc[1][0]); acc[1][1] = fma2(a1, x1, acc[1][1]);
            acc[2][0] = fma2(a2, x0, acc[2][0]); acc[2][1] = fma2(a2, x1, acc[2][1]);
            acc[3][0] = fma2(a3, x0, acc[3][0]); acc[3][1] = fma2(a3, x1, acc[3][1]);
        }
        __syncthreads();
    }
    #pragma unroll
    for (int mi = 0; mi < 4; mi++) {
        int m = m0 + tm*4 + mi;
        if (m >= M) continue;
        float bv = bias ? bias[m] : 0.f;
        float4 o4;
        unpack2(acc[mi][0], o4.x, o4.y);
        unpack2(acc[mi][1], o4.z, o4.w);
        o4.x += bv; o4.y += bv; o4.z += bv; o4.w += bv;
        if (doRelu) {
            o4.x = fmaxf(o4.x, 0.f); o4.y = fmaxf(o4.y, 0.f);
            o4.z = fmaxf(o4.z, 0.f); o4.w = fmaxf(o4.w, 0.f);
        }
        *reinterpret_cast<float4*>(&Cb[(size_t)m*Nn + n0 + tn*4]) = o4;
    }
}

// ---------------------------------------------------------------------------
// 3a. Candidate top-24, warp-per-row
// ---------------------------------------------------------------------------
__global__ __launch_bounds__(256)
void topk_cand_kernel(const float* __restrict__ dot, const float* __restrict__ sq,
                      int* __restrict__ candout) {
    int warp = threadIdx.x >> 5, lane = threadIdx.x & 31;
    int bn = blockIdx.x * 8 + warp;
    int b = bn >> 10;
    const float* drow = dot + (size_t)bn * 1024;
    const float* sqb = sq + b * 1024;
    float sqn = sqb[bn & 1023];
    float val[32];
    #pragma unroll
    for (int q = 0; q < 32; q++) {
        int m = q * 32 + lane;
        float t1 = __fadd_rn(sqn, -__fmul_rn(2.f, drow[m]));
        val[q] = -__fadd_rn(t1, sqb[m]);
    }
    float bv = val[0]; int bq = 0;
    #pragma unroll
    for (int q = 1; q < 32; q++) if (val[q] > bv) { bv = val[q]; bq = q; }
    for (int it = 0; it < NCAND; it++) {
        float v = bv; int bi = bq * 32 + lane;
        #pragma unroll
        for (int off = 16; off > 0; off >>= 1) {
            float v2 = __shfl_xor_sync(0xffffffffu, v, off);
            int   i2 = __shfl_xor_sync(0xffffffffu, bi, off);
            if (v2 > v || (v2 == v && i2 < bi)) { v = v2; bi = i2; }
        }
        if (lane == 0) candout[(size_t)bn*NCAND + it] = bi;
        if ((bi & 31) == lane) {
            int qs = bi >> 5;
            #pragma unroll
            for (int q = 0; q < 32; q++) if (q == qs) val[q] = -INFINITY;
            bv = val[0]; bq = 0;
            #pragma unroll
            for (int q = 1; q < 32; q++) if (val[q] > bv) { bv = val[q]; bq = q; }
        }
    }
}

// ---------------------------------------------------------------------------
// 3b. Refine: exact double dists, fp32-round, stable sort, top-18
// ---------------------------------------------------------------------------
__global__ __launch_bounds__(128)
void refine_topk_kernel(const double* __restrict__ xnd, const double* __restrict__ sqd,
                        const int* __restrict__ cand, int* __restrict__ idxout) {
    int bn = blockIdx.x;
    int b = bn >> 10;
    int tid = threadIdx.x, lane = tid & 31, warp = tid >> 5;
    __shared__ float scores[NCAND];
    __shared__ int   cidx[NCAND];
    if (tid < NCAND) cidx[tid] = cand[(size_t)bn*NCAND + tid];
    const double* xrp = xnd + (size_t)bn * 128 + lane * 4;
    double xr0 = xrp[0], xr1 = xrp[1], xr2 = xrp[2], xr3 = xrp[3];
    __syncthreads();
    double sqn = sqd[bn];
    for (int k = warp; k < NCAND; k += 4) {
        int m = cidx[k];
        const double* xm = xnd + ((size_t)b*NPT + m) * 128 + lane * 4;
        double s = xr0*xm[0] + xr1*xm[1] + xr2*xm[2] + xr3*xm[3];
        #pragma unroll
        for (int off = 16; off > 0; off >>= 1)
            s += __shfl_xor_sync(0xffffffffu, s, off);
        if (lane == 0)
            scores[k] = (float)(-(sqn - 2.0 * s + sqd[(size_t)b*NPT + m]));
    }
    __syncthreads();
    if (tid == 0) {
        float sc[NCAND]; int ci[NCAND];
        for (int i = 0; i < NCAND; i++) { sc[i] = scores[i]; ci[i] = cidx[i]; }
        for (int i = 1; i < NCAND; i++) {
            float sv = sc[i]; int iv = ci[i];
            int j = i - 1;
            while (j >= 0 && (sc[j] < sv || (sc[j] == sv && ci[j] > iv))) {
                sc[j+1] = sc[j]; ci[j+1] = ci[j]; j--;
            }
            sc[j+1] = sv; ci[j+1] = iv;
        }
        for (int r = 0; r < 18; r++) idxout[(size_t)bn*18 + r] = ci[r];
    }
}

// ---------------------------------------------------------------------------
// 4. FUSED edge conv v2: 64o x 64n block, 4x4 thread tile
// ---------------------------------------------------------------------------
__global__ __launch_bounds__(256)
void edge_fused_kernel(const float* __restrict__ W2, const float* __restrict__ u,
                       int uoff, const float* __restrict__ xT, const int* __restrict__ ibuf,
                       int step, float* __restrict__ Mx, float* __restrict__ part) {
    __shared__ float W2s[128][68];  // [k][m-64]
    __shared__ float Xs[32][68];    // [k][n]
    __shared__ int   js[64];
    int b = blockIdx.z, bx = blockIdx.x;
    int m0 = blockIdx.y * 64, n0 = bx * 64;
    int tid = threadIdx.x;
    int tn = tid & 15, tm = tid >> 4;
    const float* xTb = xT + (size_t)b * NPT * CIN;

    for (int i = tid; i < 64*128; i += 256) {
        int m = i >> 7, k = i & 127;
        W2s[k][m] = W2[(size_t)(m0+m)*128 + k];
    }
    float4 u4[4];
    #pragma unroll
    for (int mi = 0; mi < 4; mi++)
        u4[mi] = *reinterpret_cast<const float4*>(
            &u[((size_t)b*512 + uoff + m0 + tm*4 + mi)*NPT + n0 + tn*4]);

    float mx[4][4], s1[4] = {0,0,0,0}, s2s[4] = {0,0,0,0};
    #pragma unroll
    for (int mi = 0; mi < 4; mi++)
        #pragma unroll
        for (int q = 0; q < 4; q++) mx[mi][q] = -INFINITY;
    __syncthreads();

    for (int k = 0; k < 9; k++) {
        if (tid < 64) js[tid] = ibuf[((size_t)b*NPT + n0 + tid)*18 + k*step];
        u64 acc[4][2] = {};
        #pragma unroll
        for (int ct = 0; ct < 4; ct++) {
            __syncthreads();
            for (int i = tid; i < 32*64; i += 256) {
                int c = i & 31, n = i >> 5;
                float xj = xTb[(size_t)js[n]*128 + ct*32 + c];
                float xi = xTb[(size_t)(n0 + n)*128 + ct*32 + c];
                Xs[c][n] = __fadd_rn(xj, -xi);
            }
            __syncthreads();
            #pragma unroll
            for (int kk = 0; kk < 32; kk++) {
                float4 a4 = *reinterpret_cast<const float4*>(&W2s[ct*32+kk][tm*4]);
                u64 x0 = *reinterpret_cast<const u64*>(&Xs[kk][tn*4]);
                u64 x1 = *reinterpret_cast<const u64*>(&Xs[kk][tn*4 + 2]);
                u64 a0 = dup2(a4.x), a1 = dup2(a4.y), a2 = dup2(a4.z), a3 = dup2(a4.w);
                acc[0][0] = fma2(a0, x0, acc[0][0]); acc[0][1] = fma2(a0, x1, acc[0][1]);
                acc[1][0] = fma2(a1, x0, acc[1][0]); acc[1][1] = fma2(a1, x1, acc[1][1]);
                acc[2][0] = fma2(a2, x0, acc[2][0]); acc[2][1] = fma2(a2, x1, acc[2][1]);
                acc[3][0] = fma2(a3, x0, acc[3][0]); acc[3][1] = fma2(a3, x1, acc[3][1]);
            }
        }
        #pragma unroll
        for (int mi = 0; mi < 4; mi++) {
            float d0, d1, d2, d3;
            unpack2(acc[mi][0], d0, d1);
            unpack2(acc[mi][1], d2, d3);
            float z0 = u4[mi].x + d0, z1 = u4[mi].y + d1;
            float z2 = u4[mi].z + d2, z3 = u4[mi].w + d3;
            mx[mi][0] = fmaxf(mx[mi][0], z0); mx[mi][1] = fmaxf(mx[mi][1], z1);
            mx[mi][2] = fmaxf(mx[mi][2], z2); mx[mi][3] = fmaxf(mx[mi][3], z3);
            s1[mi]  += (z0 + z1) + (z2 + z3);
            s2s[mi] += (z0*z0 + z1*z1) + (z2*z2 + z3*z3);
        }
        __syncthreads();
    }
    #pragma unroll
    for (int mi = 0; mi < 4; mi++) {
        float4 o4 = make_float4(mx[mi][0], mx[mi][1], mx[mi][2], mx[mi][3]);
        *reinterpret_cast<float4*>(
            &Mx[((size_t)b*256 + m0 + tm*4 + mi)*NPT + n0 + tn*4]) = o4;
    }
    #pragma unroll
    for (int mi = 0; mi < 4; mi++) {
        float a = s1[mi], c2 = s2s[mi];
        #pragma unroll
        for (int off = 1; off < 16; off <<= 1) {
            a  += __shfl_xor_sync(0xffffffffu, a, off);
            c2 += __shfl_xor_sync(0xffffffffu, c2, off);
        }
        if (tn == 0) {
            int o = m0 + tm*4 + mi;
            int slot = b*16 + bx;
            part[((size_t)o*64 + slot)*2]     = a;
            part[((size_t)o*64 + slot)*2 + 1] = c2;
        }
    }
}

__global__ void finalize_edge_kernel(const float* __restrict__ partA, const float* __restrict__ partB,
                                     const float* __restrict__ gA, const float* __restrict__ btA,
                                     const float* __restrict__ gB, const float* __restrict__ btB,
                                     float* aA, float* cA, float* aB, float* cB) {
    int t = threadIdx.x;
    const float invCnt = 1.f / (float)(B * NPT * KNN);
    if (t < 256) {
        float s1 = 0.f, s2 = 0.f;
        for (int j = 0; j < 64; j++) { s1 += partA[((size_t)t*64 + j)*2]; s2 += partA[((size_t)t*64 + j)*2 + 1]; }
        float m = s1 * invCnt;
        float var = s2 * invCnt - m * m;
        float a = gA[t] * rsqrtf(var + EPS_BN);
        aA[t] = a; cA[t] = btA[t] - m * a;
    } else {
        int o = t - 256;
        float s1 = 0.f, s2 = 0.f;
        for (int j = 0; j < 64; j++) { s1 += partB[((size_t)o*64 + j)*2]; s2 += partB[((size_t)o*64 + j)*2 + 1]; }
        float m = s1 * invCnt;
        float var = s2 * invCnt - m * m;
        float a = gB[o] * rsqrtf(var + EPS_BN);
        aB[o] = a; cB[o] = btB[o] - m * a;
    }
}

// ---------------------------------------------------------------------------
// 6. Build net — elementwise
// ---------------------------------------------------------------------------
__global__ __launch_bounds__(256)
void build_net_kernel(const float* __restrict__ MxA, const float* __restrict__ MxB,
                      const float* __restrict__ aA, const float* __restrict__ cA,
                      const float* __restrict__ aB, const float* __restrict__ cB,
                      float* __restrict__ net) {
    size_t idx = (size_t)blockIdx.x * 256 + threadIdx.x;
    if (idx >= (size_t)B * 130 * MPT) return;
    int b = (int)(idx / (130 * MPT));
    int r = (int)(idx - (size_t)b * 130 * MPT);
    int c = r >> 12, m = r & 4095;
    float val;
    if (c < 128) {
        int n = m >> 2, j = m & 3;
        if (j < 2) {
            int o = j*128 + c;
            val = fmaxf(0.f, aA[o] * MxA[((size_t)b*256 + o)*NPT + n] + cA[o]);
        } else {
            int o = (j-2)*128 + c;
            val = fmaxf(0.f, aB[o] * MxB[((size_t)b*256 + o)*NPT + n] + cB[o]);
        }
    } else if (c == 128) {
        val = ((m >> 10) < 2) ? -0.2f : 0.2f;
    } else {
        val = ((m >> 10) & 1) ? 0.2f : -0.2f;
    }
    net[idx] = val;
}

// ---------------------------------------------------------------------------
// 7. FUSED attention BN stats (194 blocks) + fused normalize+relu
// ---------------------------------------------------------------------------
__global__ __launch_bounds__(256)
void stats_fused_kernel(const float* __restrict__ PFG, const float* __restrict__ Ph,
                        const float* __restrict__ gf, const float* __restrict__ bef,
                        const float* __restrict__ gg, const float* __restrict__ beg,
                        const float* __restrict__ gh, const float* __restrict__ beh,
                        float* __restrict__ scfg, float* __restrict__ bifg,
                        float* __restrict__ sch,  float* __restrict__ bih) {
    int bid = blockIdx.x;
    const float* base; int C, c; float gv, bev; float *scp, *bip;
    if (bid < 64) {
        base = PFG; C = 64; c = bid;
        gv  = (c < 32) ? gf[c]  : gg[c-32];
        bev = (c < 32) ? bef[c] : beg[c-32];
        scp = scfg; bip = bifg;
    } else {
        base = Ph; C = 130; c = bid - 64;
        gv = gh[c]; bev = beh[c];
        scp = sch; bip = bih;
    }
    int tid = threadIdx.x;
    float s1 = 0.f, s2 = 0.f;
    for (int b = 0; b < B; b++) {
        const float* p = base + ((size_t)b*C + c) * MPT;
        for (int m = tid; m < MPT; m += 256) { float v = p[m]; s1 += v; s2 += v*v; }
    }
    __shared__ float r1[256], r2[256];
    r1[tid] = s1; r2[tid] = s2;
    __syncthreads();
    for (int s = 128; s > 0; s >>= 1) {
        if (tid < s) { r1[tid] += r1[tid+s]; r2[tid] += r2[tid+s]; }
        __syncthreads();
    }
    if (tid == 0) {
        const float invCnt = 1.f / (float)(B * MPT);
        float m = r1[0] * invCnt;
        float var = r2[0] * invCnt - m * m;
        float a = gv * rsqrtf(var + EPS_BN);
        scp[c] = a; bip[c] = bev - m * a;
    }
}

__global__ void norm_relu_fused_kernel(const float* __restrict__ PFG, const float* __restrict__ Ph,
                                       const float* __restrict__ scfg, const float* __restrict__ bifg,
                                       const float* __restrict__ sch,  const float* __restrict__ bih,
                                       float* __restrict__ FG, float* __restrict__ HnB) {
    size_t idx = (size_t)blockIdx.x * 256 + threadIdx.x;
    size_t t1 = (size_t)B * 64 * MPT;
    size_t t2 = (size_t)B * 130 * MPT;
    if (idx < t1) {
        int c = (int)((idx / MPT) % 64);
        FG[idx] = fmaxf(0.f, PFG[idx] * scfg[c] + bifg[c]);
    } else if (idx < t1 + t2) {
        size_t j = idx - t1;
        int c = (int)((j / MPT) % 130);
        HnB[j] = fmaxf(0.f, Ph[j] * sch[c] + bih[c]);
    }
}

// ---------------------------------------------------------------------------
// 8. Attention pass 1 (R6 core): 16 rows/block; F,G from FG buffer.
// ---------------------------------------------------------------------------
__global__ __launch_bounds__(256)
void att_pass1_kernel(const float* __restrict__ FG,
                      float* __restrict__ rmax, float* __restrict__ rinv) {
    int b = blockIdx.y;
    int n0 = blockIdx.x * 16;
    const float* F = FG + (size_t)b * 64 * MPT;
    const float* G = F + (size_t)32 * MPT;
    __shared__ u64 Gs2[16][17];
    __shared__ float smx[16][256];
    __shared__ float ssm[16][256];
    int tid = threadIdx.x;
    {
        int cp = tid >> 4, r = tid & 15;
        float g0 = G[(size_t)(2*cp) * MPT + n0 + r];
        float g1 = G[(size_t)(2*cp + 1) * MPT + n0 + r];
        Gs2[cp][r] = pack2(g0, g1);
    }
    __syncthreads();
    float mx[16], sm[16];
    #pragma unroll
    for (int r = 0; r < 16; r++) { mx[r] = -INFINITY; sm[r] = 0.f; }
    for (int j = 0; j < 16; j++) {
        int m = tid + j * 256;
        u64 fp2[16];
        #pragma unroll
        for (int cp = 0; cp < 16; cp++) {
            float f0 = F[(size_t)(2*cp) * MPT + m];
            float f1 = F[(size_t)(2*cp + 1) * MPT + m];
            fp2[cp] = pack2(f0, f1);
        }
        #pragma unroll
        for (int r = 0; r < 16; r++) {
            u64 sacc = 0;
            #pragma unroll
            for (int cp = 0; cp < 16; cp++) sacc = fma2(fp2[cp], Gs2[cp][r], sacc);
            float s0, s1v; unpack2(sacc, s0, s1v);
            float s = s0 + s1v;
            if (s > mx[r]) { sm[r] = sm[r] * __expf(mx[r] - s) + 1.f; mx[r] = s; }
            else           { sm[r] += __expf(s - mx[r]); }
        }
    }
    #pragma unroll
    for (int r = 0; r < 16; r++) { smx[r][tid] = mx[r]; ssm[r][tid] = sm[r]; }
    __syncthreads();
    int w = tid >> 5, lane = tid & 31;
    for (int rr = w; rr < 16; rr += 8) {
        float M = -INFINITY, S = 0.f;
        for (int e = lane; e < 256; e += 32) {
            float m2 = smx[rr][e], s2 = ssm[rr][e];
            if (m2 > M) { S = S * __expf(M - m2) + s2; M = m2; }
            else        { S += s2 * __expf(m2 - M); }
        }
        #pragma unroll
        for (int o = 16; o > 0; o >>= 1) {
            float m2 = __shfl_xor_sync(0xffffffffu, M, o);
            float s2 = __shfl_xor_sync(0xffffffffu, S, o);
            if (m2 > M) { S = S * __expf(M - m2) + s2; M = m2; }
            else        { S += s2 * __expf(m2 - M); }
        }
        if (lane == 0) {
            rmax[(size_t)b*MPT + n0 + rr] = M;
            rinv[(size_t)b*MPT + n0 + rr] = __fdiv_rn(1.f, S);
        }
    }
}

// ---------------------------------------------------------------------------
// 9. Attention pass 2 (R10 core): warp owns 17 channels, lane owns 4 m;
//    Hs2 [c][j] conflict-free layout, rinv folded during staging.
//    Idempotent: reads FG/Hn/rmax/rinv/net, writes net2 only.
// ---------------------------------------------------------------------------
constexpr int P2_SMEM = 136*33*8 + 32*130*4 + 32*130*4 + 32*33*4 + 32*4;

__global__ __launch_bounds__(256, 1)
void att_pass2_kernel(const float* __restrict__ FG, const float* __restrict__ Hn,
                      const float* __restrict__ rmax, const float* __restrict__ rinv,
                      const float* __restrict__ net, const float* __restrict__ gamma,
                      float* __restrict__ net2) {
    extern __shared__ char smem_raw[];
    u64*   Hs2 = reinterpret_cast<u64*>(smem_raw);       // [136][33] dup(h*rinv)
    float* Fs  = reinterpret_cast<float*>(Hs2 + 136*33); // [32][130]
    float* es  = Fs + 32*130;                            // [32][130]
    float* Gs  = es + 32*130;                            // [32][33]
    float* rmx = Gs + 32*33;                             // [32]

    int b = blockIdx.y;
    int m0 = blockIdx.x * 128;
    int tid = threadIdx.x;
    int w = tid >> 5, lane = tid & 31;
    int c0 = w * 17;
    const float* F = FG + (size_t)b * 64 * MPT;
    const float* G = F + (size_t)32 * MPT;

    for (int idx = tid; idx < 32*128; idx += 256) {
        int c = idx >> 7, mm = idx & 127;
        Fs[c*130 + mm] = F[(size_t)c * MPT + m0 + mm];
    }
    u64 acc2[17][2];
    #pragma unroll
    for (int i = 0; i < 17; i++) { acc2[i][0] = 0; acc2[i][1] = 0; }

    for (int nt = 0; nt < 128; nt++) {
        int n0v = nt * 32;
        __syncthreads();
        if (tid < 32) rmx[tid] = rmax[(size_t)b*MPT + n0v + tid];
        for (int idx = tid; idx < 32*32; idx += 256) {
            int c = idx >> 5, jj = idx & 31;
            Gs[c*33 + jj] = G[(size_t)c * MPT + n0v + jj];
        }
        for (int idx = tid; idx < 136*32; idx += 256) {
            int c = idx >> 5, jj = idx & 31;
            float h = 0.f;
            if (c < 130)
                h = Hn[((size_t)b*130 + c) * MPT + n0v + jj] * rinv[(size_t)b*MPT + n0v + jj];
            Hs2[c*33 + jj] = dup2(h);
        }
        __syncthreads();
        // s-phase
        {
            int nl = tid & 31, mg = tid >> 5;
            float gc[32];
            #pragma unroll
            for (int c = 0; c < 32; c++) gc[c] = Gs[c*33 + nl];
            float rm = rmx[nl];
            #pragma unroll
            for (int q = 0; q < 8; q++) {
                int mm = mg*16 + 2*q;
                u64 sacc = 0;
                #pragma unroll
                for (int c = 0; c < 32; c++)
                    sacc = fma2(dup2(gc[c]), *reinterpret_cast<const u64*>(&Fs[c*130 + mm]), sacc);
                float s0, s1v; unpack2(sacc, s0, s1v);
                es[nl*130 + mm]     = __expf(s0 - rm);
                es[nl*130 + mm + 1] = __expf(s1v - rm);
            }
        }
        __syncthreads();
        // o-phase
        #pragma unroll 4
        for (int j = 0; j < 32; j++) {
            u64 e01 = *reinterpret_cast<const u64*>(&es[j*130 + 4*lane]);
            u64 e23 = *reinterpret_cast<const u64*>(&es[j*130 + 4*lane + 2]);
            #pragma unroll
            for (int i = 0; i < 17; i++) {
                u64 h2 = Hs2[(c0 + i)*33 + j];
                acc2[i][0] = fma2(h2, e01, acc2[i][0]);
                acc2[i][1] = fma2(h2, e23, acc2[i][1]);
            }
        }
    }
    float gm = gamma[0];
    #pragma unroll
    for (int i = 0; i < 17; i++) {
        int c = c0 + i;
        if (c >= 130) break;
        size_t off = ((size_t)b*130 + c) * MPT + m0 + 4*lane;
        float a0, a1, a2, a3;
        unpack2(acc2[i][0], a0, a1);
        unpack2(acc2[i][1], a2, a3);
        net2[off]     = gm * a0 + net[off];
        net2[off + 1] = gm * a1 + net[off + 1];
        net2[off + 2] = gm * a2 + net[off + 2];
        net2[off + 3] = gm * a3 + net[off + 3];
    }
}

// ---------------------------------------------------------------------------
// Host launch
// ---------------------------------------------------------------------------
extern "C" void kernel_launch(void* const* d_in, const int* in_sizes, int n_in,
                              void* d_out, int out_size) {
    float* buf = nullptr; int* ibuf = nullptr; int* candb = nullptr; double* dbuf = nullptr;
    cudaGetSymbolAddress((void**)&buf,   g_buf);
    cudaGetSymbolAddress((void**)&ibuf,  g_ibuf);
    cudaGetSymbolAddress((void**)&candb, g_cand);
    cudaGetSymbolAddress((void**)&dbuf,  g_dbuf);
    cudaFuncSetAttribute(att_pass2_kernel, cudaFuncAttributeMaxDynamicSharedMemorySize, P2_SMEM);

    const float* inp  = (const float*)d_in[0];
    const float* Wa   = (const float*)d_in[1];
    const float* gna  = (const float*)d_in[2];
    const float* bta  = (const float*)d_in[3];
    const float* Wb   = (const float*)d_in[4];
    const float* gnb  = (const float*)d_in[5];
    const float* btb  = (const float*)d_in[6];
    const float* Wf   = (const float*)d_in[7];
    const float* gf   = (const float*)d_in[9];
    const float* bef  = (const float*)d_in[10];
    const float* Wg   = (const float*)d_in[11];
    const float* gg   = (const float*)d_in[13];
    const float* beg  = (const float*)d_in[14];
    const float* Wh   = (const float*)d_in[15];
    const float* gh   = (const float*)d_in[17];
    const float* beh  = (const float*)d_in[18];
    const float* gamma= (const float*)d_in[19];
    const float* W1   = (const float*)d_in[20];
    const float* b1   = (const float*)d_in[21];
    const float* W2   = (const float*)d_in[22];
    const float* b2   = (const float*)d_in[23];
    float* out = (float*)d_out;

    float *xn   = buf + O_XN,   *xnT  = buf + O_XNT, *xTr = buf + O_XTR, *sq = buf + O_SQ;
    float *dot  = buf + O_DOT;
    float *W1AB = buf + O_W1AB, *W2A  = buf + O_W2A, *W2B = buf + O_W2B, *WFG = buf + O_WFG;
    float *U    = buf + O_U;
    float *MxA  = buf + O_MXA,  *MxB  = buf + O_MXB;
    float *partA= buf + O_PARTA,*partB= buf + O_PARTB;
    float *aA   = buf + O_AA,   *cA   = buf + O_CA,  *aB  = buf + O_AB2, *cB = buf + O_CB2;
    float *net  = buf + O_NET;
    float *PFG  = buf + O_PFG,  *Ph   = buf + O_PH;
    float *FG   = buf + O_FG,   *HnB  = buf + O_HN;
    float *scfg = buf + O_SCFG, *bifg = buf + O_BIFG;
    float *sch  = buf + O_SCH,  *bih  = buf + O_BIH;
    float *rmax = buf + O_RMAX, *rinv = buf + O_RINV;
    float *net2 = buf + O_NET2, *y1   = buf + O_Y1;
    double *xnd = dbuf;
    double *sqd = dbuf + (size_t)B*NPT*CIN;

    prep_w_kernel<<<545, 256>>>(Wa, Wb, Wf, Wg, W1AB, W2A, W2B, WFG);
    normalize_kernel<<<(B*NPT*32)/256, 256>>>(inp, xn, xnT, xTr, sq, xnd, sqd);
    gemm_kernel<<<dim3(NPT/64, 8, B), 256>>>(W1AB, 0, inp, nullptr, U, 512, CIN, NPT, 0);
    gemm_kernel<<<dim3(NPT/64, NPT/64, B), 256>>>(xnT, (size_t)NPT*CIN, xn, nullptr, dot, NPT, CIN, NPT, 0);
    topk_cand_kernel<<<(B*NPT)/8, 256>>>(dot, sq, candb);
    refine_topk_kernel<<<B*NPT, 128>>>(xnd, sqd, candb, ibuf);
    edge_fused_kernel<<<dim3(16, 4, B), 256>>>(W2A, U, 0,   xTr, ibuf, 1, MxA, partA);
    edge_fused_kernel<<<dim3(16, 4, B), 256>>>(W2B, U, 256, xTr, ibuf, 2, MxB, partB);
    finalize_edge_kernel<<<1, 512>>>(partA, partB, gna, bta, gnb, btb, aA, cA, aB, cB);
    build_net_kernel<<<(unsigned)(((size_t)B*130*MPT + 255)/256), 256>>>(MxA, MxB, aA, cA, aB, cB, net);
    gemm_kernel<<<dim3(MPT/64, 1, B), 256>>>(WFG, 0, net, nullptr, PFG, 64, 130, MPT, 0);
    gemm_kernel<<<dim3(MPT/64, 3, B), 256>>>(Wh, 0, net, nullptr, Ph, 130, 130, MPT, 0);
    stats_fused_kernel<<<194, 256>>>(PFG, Ph, gf, bef, gg, beg, gh, beh, scfg, bifg, sch, bih);
    {
        size_t tot = (size_t)B*64*MPT + (size_t)B*130*MPT;
        norm_relu_fused_kernel<<<(unsigned)((tot + 255)/256), 256>>>(PFG, Ph, scfg, bifg, sch, bih, FG, HnB);
    }
    att_pass1_kernel<<<dim3(MPT/16, B), 256>>>(FG, rmax, rinv);
    // pass2 launched TWICE (idempotent) — dur delta vs R13 == pass2 wall cost.
    att_pass2_kernel<<<dim3(MPT/128, B), 256, P2_SMEM>>>(FG, HnB, rmax, rinv, net, gamma, net2);
    att_pass2_kernel<<<dim3(MPT/128, B), 256, P2_SMEM>>>(FG, HnB, rmax, rinv, net, gamma, net2);
    gemm_kernel<<<dim3(MPT/64, 4, B), 256>>>(W1, 0, net2, b1, y1, 256, 130, MPT, 1);
    gemm_kernel<<<dim3(MPT/64, 2, B), 256>>>(W2, 0, y1, b2, out, 128, 256, MPT, 1);
}

// round 15
// speedup vs baseline: 1.3671x; 1.3671x over previous
#include <cuda_runtime.h>
#include <cstdint>
#include <cstddef>

// ---------------------------------------------------------------------------
// Problem constants
// ---------------------------------------------------------------------------
constexpr int B    = 4;
constexpr int CIN  = 128;
constexpr int NPT  = 1024;   // points
constexpr int KNN  = 9;
constexpr int MPT  = 4096;   // upsampled points = 4*N
constexpr int NCAND = 24;    // fp32 candidate shortlist size
constexpr float EPS_BN = 1e-5f;

// ---------------------------------------------------------------------------
// f32x2 packed-FMA helpers
// ---------------------------------------------------------------------------
using u64 = unsigned long long;
__device__ __forceinline__ u64 dup2(float v) {
    u64 r; asm("mov.b64 %0, {%1, %1};" : "=l"(r) : "f"(v)); return r;
}
__device__ __forceinline__ u64 pack2(float a, float b) {
    u64 r; asm("mov.b64 %0, {%1, %2};" : "=l"(r) : "f"(a), "f"(b)); return r;
}
__device__ __forceinline__ u64 fma2(u64 a, u64 b, u64 c) {
    u64 d; asm("fma.rn.f32x2 %0, %1, %2, %3;" : "=l"(d) : "l"(a), "l"(b), "l"(c)); return d;
}
__device__ __forceinline__ void unpack2(u64 v, float& lo, float& hi) {
    asm("mov.b64 {%0, %1}, %2;" : "=f"(lo), "=f"(hi) : "l"(v));
}

// ---------------------------------------------------------------------------
// Scratch buffer offsets (floats)
// ---------------------------------------------------------------------------
constexpr size_t SZ_XN   = (size_t)B*CIN*NPT;
constexpr size_t SZ_SQ   = (size_t)B*NPT;
constexpr size_t SZ_DOT  = (size_t)B*NPT*NPT;
constexpr size_t SZ_U    = (size_t)B*512*NPT;
constexpr size_t SZ_UV   = (size_t)B*256*NPT;
constexpr size_t SZ_PART = 256*64*2;
constexpr size_t SZ_NET  = (size_t)B*130*MPT;
constexpr size_t SZ_PFG  = (size_t)B*64*MPT;
constexpr size_t SZ_ROW  = (size_t)B*MPT;
constexpr size_t SZ_Y1   = (size_t)B*256*MPT;

constexpr size_t O_XN    = 0;
constexpr size_t O_XNT   = O_XN   + SZ_XN;
constexpr size_t O_XTR   = O_XNT  + SZ_XN;
constexpr size_t O_SQ    = O_XTR  + SZ_XN;
constexpr size_t O_DOT   = O_SQ   + SZ_SQ;
constexpr size_t O_W1AB  = O_DOT  + SZ_DOT;            // [512][128]
constexpr size_t O_W2A   = O_W1AB + 512*128;
constexpr size_t O_W2B   = O_W2A  + 256*128;
constexpr size_t O_WFG   = O_W2B  + 256*128;           // [64][130]
constexpr size_t O_U     = O_WFG  + 64*130;            // [B][512][NPT]
constexpr size_t O_MXA   = O_U    + SZ_U;
constexpr size_t O_MXB   = O_MXA  + SZ_UV;
constexpr size_t O_PARTA = O_MXB  + SZ_UV;
constexpr size_t O_PARTB = O_PARTA+ SZ_PART;
constexpr size_t O_AA    = O_PARTB+ SZ_PART;
constexpr size_t O_CA    = O_AA   + 256;
constexpr size_t O_AB2   = O_CA   + 256;
constexpr size_t O_CB2   = O_AB2  + 256;
constexpr size_t O_NET   = O_CB2  + 256;
constexpr size_t O_PFG   = O_NET  + SZ_NET;            // [B][64][MPT]
constexpr size_t O_PH    = O_PFG  + SZ_PFG;            // [B][130][MPT]
constexpr size_t O_FG    = O_PH   + SZ_NET;            // [B][64][MPT]
constexpr size_t O_HN    = O_FG   + SZ_PFG;            // [B][130][MPT]
constexpr size_t O_SCFG  = O_HN   + SZ_NET;
constexpr size_t O_BIFG  = O_SCFG + 64;
constexpr size_t O_SCH   = O_BIFG + 64;
constexpr size_t O_BIH   = O_SCH  + 130;
constexpr size_t O_RMAX  = O_BIH  + 130;
constexpr size_t O_RINV  = O_RMAX + SZ_ROW;
constexpr size_t O_NET2  = O_RINV + SZ_ROW;
constexpr size_t O_Y1    = O_NET2 + SZ_NET;
constexpr size_t O_END   = O_Y1   + SZ_Y1;

__device__ float  g_buf[O_END];
__device__ int    g_ibuf[(size_t)B*NPT*18];
__device__ int    g_cand[(size_t)B*NPT*NCAND];
__device__ double g_dbuf[(size_t)B*NPT*CIN + (size_t)B*NPT];

// ---------------------------------------------------------------------------
// 0. Weight prep: W1AB=[Wa1;Wb1] (512x128), W2A/W2B (256x128), WFG=[Wf;Wg]
// ---------------------------------------------------------------------------
__global__ void prep_w_kernel(const float* __restrict__ Wa, const float* __restrict__ Wb,
                              const float* __restrict__ Wf, const float* __restrict__ Wg,
                              float* W1AB, float* W2A, float* W2B, float* WFG) {
    int idx = blockIdx.x * 256 + threadIdx.x;
    if (idx < 65536) {
        int o = idx >> 7, c = idx & 127;
        W1AB[idx] = (o < 256) ? Wa[o*256 + c] : Wb[(o-256)*256 + c];
    } else if (idx < 98304) {
        int j = idx - 65536; int o = j >> 7, c = j & 127;
        W2A[j] = Wa[o*256 + 128 + c];
    } else if (idx < 131072) {
        int j = idx - 98304; int o = j >> 7, c = j & 127;
        W2B[j] = Wb[o*256 + 128 + c];
    } else if (idx < 131072 + 64*130) {
        int j = idx - 131072;
        WFG[j] = (j < 32*130) ? Wf[j] : Wg[j - 32*130];
    }
}

// ---------------------------------------------------------------------------
// 1. Normalize in DOUBLE, warp-per-point
// ---------------------------------------------------------------------------
__global__ __launch_bounds__(256)
void normalize_kernel(const float* __restrict__ x,
                      float* __restrict__ xn, float* __restrict__ xnT,
                      float* __restrict__ xTr, float* __restrict__ sq,
                      double* __restrict__ xnd, double* __restrict__ sqd) {
    int gw = (blockIdx.x * 256 + threadIdx.x) >> 5;
    if (gw >= B * NPT) return;
    int lane = threadIdx.x & 31;
    int b = gw >> 10, n = gw & 1023;
    const float* xp = x + (size_t)b * CIN * NPT + n;
    float vf[4];
    double ss = 0.0;
    #pragma unroll
    for (int i = 0; i < 4; i++) {
        float v = xp[(size_t)(i*32 + lane) * NPT];
        vf[i] = v;
        ss += (double)v * (double)v;
    }
    #pragma unroll
    for (int off = 16; off > 0; off >>= 1)
        ss += __shfl_xor_sync(0xffffffffu, ss, off);
    double nrm = sqrt(ss); if (nrm < 1e-12) nrm = 1e-12;
    double inv = 1.0 / nrm;
    double s2 = 0.0;
    #pragma unroll
    for (int i = 0; i < 4; i++) {
        int c = i*32 + lane;
        double v = (double)vf[i] * inv;
        xn[((size_t)b*CIN + c) * NPT + n] = (float)v;
        xnT[((size_t)b*NPT + n) * CIN + c] = (float)v;
        xTr[((size_t)b*NPT + n) * CIN + c] = vf[i];
        xnd[((size_t)b*NPT + n) * CIN + c] = v;
        s2 += v * v;
    }
    #pragma unroll
    for (int off = 16; off > 0; off >>= 1)
        s2 += __shfl_xor_sync(0xffffffffu, s2, off);
    if (lane == 0) { sq[gw] = (float)s2; sqd[gw] = s2; }
}

// ---------------------------------------------------------------------------
// 2. Tiled GEMM v2: 64x64 block, 4m x 4n per thread
// ---------------------------------------------------------------------------
__global__ __launch_bounds__(256)
void gemm_kernel(const float* __restrict__ A, size_t aStride,
                 const float* __restrict__ X, const float* __restrict__ bias,
                 float* __restrict__ C, int M, int K, int Nn, int doRelu) {
    __shared__ float As[32][68];   // [k][m]
    __shared__ float Xs[32][68];   // [k][n]
    int b = blockIdx.z;
    const float* Ab = A + (size_t)b * aStride;
    const float* Xb = X + (size_t)b * K * Nn;
    float* Cb = C + (size_t)b * M * Nn;
    int m0 = blockIdx.y * 64, n0 = blockIdx.x * 64;
    int tid = threadIdx.x;
    int tn = tid & 15, tm = tid >> 4;
    u64 acc[4][2] = {};
    int kTiles = (K + 31) / 32;
    for (int kt = 0; kt < kTiles; kt++) {
        int k0 = kt * 32;
        for (int i = tid; i < 64*32; i += 256) {
            int m = i >> 5, k = i & 31;
            float v = 0.f;
            if (m0 + m < M && k0 + k < K) v = Ab[(size_t)(m0+m)*K + k0 + k];
            As[k][m] = v;
        }
        for (int i = tid; i < 32*64; i += 256) {
            int k = i >> 6, n = i & 63;
            float v = 0.f;
            if (k0 + k < K) v = Xb[(size_t)(k0+k)*Nn + n0 + n];
            Xs[k][n] = v;
        }
        __syncthreads();
        #pragma unroll
        for (int kk = 0; kk < 32; kk++) {
            float4 a4 = *reinterpret_cast<const float4*>(&As[kk][tm*4]);
            u64 x0 = *reinterpret_cast<const u64*>(&Xs[kk][tn*4]);
            u64 x1 = *reinterpret_cast<const u64*>(&Xs[kk][tn*4 + 2]);
            u64 a0 = dup2(a4.x), a1 = dup2(a4.y), a2 = dup2(a4.z), a3 = dup2(a4.w);
            acc[0][0] = fma2(a0, x0, acc[0][0]); acc[0][1] = fma2(a0, x1, acc[0][1]);
            acc[1][0] = fma2(a1, x0, acc[1][0]); acc[1][1] = fma2(a1, x1, acc[1][1]);
            acc[2][0] = fma2(a2, x0, acc[2][0]); acc[2][1] = fma2(a2, x1, acc[2][1]);
            acc[3][0] = fma2(a3, x0, acc[3][0]); acc[3][1] = fma2(a3, x1, acc[3][1]);
        }
        __syncthreads();
    }
    #pragma unroll
    for (int mi = 0; mi < 4; mi++) {
        int m = m0 + tm*4 + mi;
        if (m >= M) continue;
        float bv = bias ? bias[m] : 0.f;
        float4 o4;
        unpack2(acc[mi][0], o4.x, o4.y);
        unpack2(acc[mi][1], o4.z, o4.w);
        o4.x += bv; o4.y += bv; o4.z += bv; o4.w += bv;
        if (doRelu) {
            o4.x = fmaxf(o4.x, 0.f); o4.y = fmaxf(o4.y, 0.f);
            o4.z = fmaxf(o4.z, 0.f); o4.w = fmaxf(o4.w, 0.f);
        }
        *reinterpret_cast<float4*>(&Cb[(size_t)m*Nn + n0 + tn*4]) = o4;
    }
}

// ---------------------------------------------------------------------------
// 3a. Candidate top-24, warp-per-row
// ---------------------------------------------------------------------------
__global__ __launch_bounds__(256)
void topk_cand_kernel(const float* __restrict__ dot, const float* __restrict__ sq,
                      int* __restrict__ candout) {
    int warp = threadIdx.x >> 5, lane = threadIdx.x & 31;
    int bn = blockIdx.x * 8 + warp;
    int b = bn >> 10;
    const float* drow = dot + (size_t)bn * 1024;
    const float* sqb = sq + b * 1024;
    float sqn = sqb[bn & 1023];
    float val[32];
    #pragma unroll
    for (int q = 0; q < 32; q++) {
        int m = q * 32 + lane;
        float t1 = __fadd_rn(sqn, -__fmul_rn(2.f, drow[m]));
        val[q] = -__fadd_rn(t1, sqb[m]);
    }
    float bv = val[0]; int bq = 0;
    #pragma unroll
    for (int q = 1; q < 32; q++) if (val[q] > bv) { bv = val[q]; bq = q; }
    for (int it = 0; it < NCAND; it++) {
        float v = bv; int bi = bq * 32 + lane;
        #pragma unroll
        for (int off = 16; off > 0; off >>= 1) {
            float v2 = __shfl_xor_sync(0xffffffffu, v, off);
            int   i2 = __shfl_xor_sync(0xffffffffu, bi, off);
            if (v2 > v || (v2 == v && i2 < bi)) { v = v2; bi = i2; }
        }
        if (lane == 0) candout[(size_t)bn*NCAND + it] = bi;
        if ((bi & 31) == lane) {
            int qs = bi >> 5;
            #pragma unroll
            for (int q = 0; q < 32; q++) if (q == qs) val[q] = -INFINITY;
            bv = val[0]; bq = 0;
            #pragma unroll
            for (int q = 1; q < 32; q++) if (val[q] > bv) { bv = val[q]; bq = q; }
        }
    }
}

// ---------------------------------------------------------------------------
// 3b. Refine: exact double dists, fp32-round, stable sort, top-18
// ---------------------------------------------------------------------------
__global__ __launch_bounds__(128)
void refine_topk_kernel(const double* __restrict__ xnd, const double* __restrict__ sqd,
                        const int* __restrict__ cand, int* __restrict__ idxout) {
    int bn = blockIdx.x;
    int b = bn >> 10;
    int tid = threadIdx.x, lane = tid & 31, warp = tid >> 5;
    __shared__ float scores[NCAND];
    __shared__ int   cidx[NCAND];
    if (tid < NCAND) cidx[tid] = cand[(size_t)bn*NCAND + tid];
    const double* xrp = xnd + (size_t)bn * 128 + lane * 4;
    double xr0 = xrp[0], xr1 = xrp[1], xr2 = xrp[2], xr3 = xrp[3];
    __syncthreads();
    double sqn = sqd[bn];
    for (int k = warp; k < NCAND; k += 4) {
        int m = cidx[k];
        const double* xm = xnd + ((size_t)b*NPT + m) * 128 + lane * 4;
        double s = xr0*xm[0] + xr1*xm[1] + xr2*xm[2] + xr3*xm[3];
        #pragma unroll
        for (int off = 16; off > 0; off >>= 1)
            s += __shfl_xor_sync(0xffffffffu, s, off);
        if (lane == 0)
            scores[k] = (float)(-(sqn - 2.0 * s + sqd[(size_t)b*NPT + m]));
    }
    __syncthreads();
    if (tid == 0) {
        float sc[NCAND]; int ci[NCAND];
        for (int i = 0; i < NCAND; i++) { sc[i] = scores[i]; ci[i] = cidx[i]; }
        for (int i = 1; i < NCAND; i++) {
            float sv = sc[i]; int iv = ci[i];
            int j = i - 1;
            while (j >= 0 && (sc[j] < sv || (sc[j] == sv && ci[j] > iv))) {
                sc[j+1] = sc[j]; ci[j+1] = ci[j]; j--;
            }
            sc[j+1] = sv; ci[j+1] = iv;
        }
        for (int r = 0; r < 18; r++) idxout[(size_t)bn*18 + r] = ci[r];
    }
}

// ---------------------------------------------------------------------------
// 4. FUSED edge conv v2: 64o x 64n block, 4x4 thread tile
// ---------------------------------------------------------------------------
__global__ __launch_bounds__(256)
void edge_fused_kernel(const float* __restrict__ W2, const float* __restrict__ u,
                       int uoff, const float* __restrict__ xT, const int* __restrict__ ibuf,
                       int step, float* __restrict__ Mx, float* __restrict__ part) {
    __shared__ float W2s[128][68];  // [k][m-64]
    __shared__ float Xs[32][68];    // [k][n]
    __shared__ int   js[64];
    int b = blockIdx.z, bx = blockIdx.x;
    int m0 = blockIdx.y * 64, n0 = bx * 64;
    int tid = threadIdx.x;
    int tn = tid & 15, tm = tid >> 4;
    const float* xTb = xT + (size_t)b * NPT * CIN;

    for (int i = tid; i < 64*128; i += 256) {
        int m = i >> 7, k = i & 127;
        W2s[k][m] = W2[(size_t)(m0+m)*128 + k];
    }
    float4 u4[4];
    #pragma unroll
    for (int mi = 0; mi < 4; mi++)
        u4[mi] = *reinterpret_cast<const float4*>(
            &u[((size_t)b*512 + uoff + m0 + tm*4 + mi)*NPT + n0 + tn*4]);

    float mx[4][4], s1[4] = {0,0,0,0}, s2s[4] = {0,0,0,0};
    #pragma unroll
    for (int mi = 0; mi < 4; mi++)
        #pragma unroll
        for (int q = 0; q < 4; q++) mx[mi][q] = -INFINITY;
    __syncthreads();

    for (int k = 0; k < 9; k++) {
        if (tid < 64) js[tid] = ibuf[((size_t)b*NPT + n0 + tid)*18 + k*step];
        u64 acc[4][2] = {};
        #pragma unroll
        for (int ct = 0; ct < 4; ct++) {
            __syncthreads();
            for (int i = tid; i < 32*64; i += 256) {
                int c = i & 31, n = i >> 5;
                float xj = xTb[(size_t)js[n]*128 + ct*32 + c];
                float xi = xTb[(size_t)(n0 + n)*128 + ct*32 + c];
                Xs[c][n] = __fadd_rn(xj, -xi);
            }
            __syncthreads();
            #pragma unroll
            for (int kk = 0; kk < 32; kk++) {
                float4 a4 = *reinterpret_cast<const float4*>(&W2s[ct*32+kk][tm*4]);
                u64 x0 = *reinterpret_cast<const u64*>(&Xs[kk][tn*4]);
                u64 x1 = *reinterpret_cast<const u64*>(&Xs[kk][tn*4 + 2]);
                u64 a0 = dup2(a4.x), a1 = dup2(a4.y), a2 = dup2(a4.z), a3 = dup2(a4.w);
                acc[0][0] = fma2(a0, x0, acc[0][0]); acc[0][1] = fma2(a0, x1, acc[0][1]);
                acc[1][0] = fma2(a1, x0, acc[1][0]); acc[1][1] = fma2(a1, x1, acc[1][1]);
                acc[2][0] = fma2(a2, x0, acc[2][0]); acc[2][1] = fma2(a2, x1, acc[2][1]);
                acc[3][0] = fma2(a3, x0, acc[3][0]); acc[3][1] = fma2(a3, x1, acc[3][1]);
            }
        }
        #pragma unroll
        for (int mi = 0; mi < 4; mi++) {
            float d0, d1, d2, d3;
            unpack2(acc[mi][0], d0, d1);
            unpack2(acc[mi][1], d2, d3);
            float z0 = u4[mi].x + d0, z1 = u4[mi].y + d1;
            float z2 = u4[mi].z + d2, z3 = u4[mi].w + d3;
            mx[mi][0] = fmaxf(mx[mi][0], z0); mx[mi][1] = fmaxf(mx[mi][1], z1);
            mx[mi][2] = fmaxf(mx[mi][2], z2); mx[mi][3] = fmaxf(mx[mi][3], z3);
            s1[mi]  += (z0 + z1) + (z2 + z3);
            s2s[mi] += (z0*z0 + z1*z1) + (z2*z2 + z3*z3);
        }
        __syncthreads();
    }
    #pragma unroll
    for (int mi = 0; mi < 4; mi++) {
        float4 o4 = make_float4(mx[mi][0], mx[mi][1], mx[mi][2], mx[mi][3]);
        *reinterpret_cast<float4*>(
            &Mx[((size_t)b*256 + m0 + tm*4 + mi)*NPT + n0 + tn*4]) = o4;
    }
    #pragma unroll
    for (int mi = 0; mi < 4; mi++) {
        float a = s1[mi], c2 = s2s[mi];
        #pragma unroll
        for (int off = 1; off < 16; off <<= 1) {
            a  += __shfl_xor_sync(0xffffffffu, a, off);
            c2 += __shfl_xor_sync(0xffffffffu, c2, off);
        }
        if (tn == 0) {
            int o = m0 + tm*4 + mi;
            int slot = b*16 + bx;
            part[((size_t)o*64 + slot)*2]     = a;
            part[((size_t)o*64 + slot)*2 + 1] = c2;
        }
    }
}

__global__ void finalize_edge_kernel(const float* __restrict__ partA, const float* __restrict__ partB,
                                     const float* __restrict__ gA, const float* __restrict__ btA,
                                     const float* __restrict__ gB, const float* __restrict__ btB,
                                     float* aA, float* cA, float* aB, float* cB) {
    int t = threadIdx.x;
    const float invCnt = 1.f / (float)(B * NPT * KNN);
    if (t < 256) {
        float s1 = 0.f, s2 = 0.f;
        for (int j = 0; j < 64; j++) { s1 += partA[((size_t)t*64 + j)*2]; s2 += partA[((size_t)t*64 + j)*2 + 1]; }
        float m = s1 * invCnt;
        float var = s2 * invCnt - m * m;
        float a = gA[t] * rsqrtf(var + EPS_BN);
        aA[t] = a; cA[t] = btA[t] - m * a;
    } else {
        int o = t - 256;
        float s1 = 0.f, s2 = 0.f;
        for (int j = 0; j < 64; j++) { s1 += partB[((size_t)o*64 + j)*2]; s2 += partB[((size_t)o*64 + j)*2 + 1]; }
        float m = s1 * invCnt;
        float var = s2 * invCnt - m * m;
        float a = gB[o] * rsqrtf(var + EPS_BN);
        aB[o] = a; cB[o] = btB[o] - m * a;
    }
}

// ---------------------------------------------------------------------------
// 6. Build net — elementwise
// ---------------------------------------------------------------------------
__global__ __launch_bounds__(256)
void build_net_kernel(const float* __restrict__ MxA, const float* __restrict__ MxB,
                      const float* __restrict__ aA, const float* __restrict__ cA,
                      const float* __restrict__ aB, const float* __restrict__ cB,
                      float* __restrict__ net) {
    size_t idx = (size_t)blockIdx.x * 256 + threadIdx.x;
    if (idx >= (size_t)B * 130 * MPT) return;
    int b = (int)(idx / (130 * MPT));
    int r = (int)(idx - (size_t)b * 130 * MPT);
    int c = r >> 12, m = r & 4095;
    float val;
    if (c < 128) {
        int n = m >> 2, j = m & 3;
        if (j < 2) {
            int o = j*128 + c;
            val = fmaxf(0.f, aA[o] * MxA[((size_t)b*256 + o)*NPT + n] + cA[o]);
        } else {
            int o = (j-2)*128 + c;
            val = fmaxf(0.f, aB[o] * MxB[((size_t)b*256 + o)*NPT + n] + cB[o]);
        }
    } else if (c == 128) {
        val = ((m >> 10) < 2) ? -0.2f : 0.2f;
    } else {
        val = ((m >> 10) & 1) ? 0.2f : -0.2f;
    }
    net[idx] = val;
}

// ---------------------------------------------------------------------------
// 7. FUSED attention BN stats (194 blocks) + fused normalize+relu
// ---------------------------------------------------------------------------
__global__ __launch_bounds__(256)
void stats_fused_kernel(const float* __restrict__ PFG, const float* __restrict__ Ph,
                        const float* __restrict__ gf, const float* __restrict__ bef,
                        const float* __restrict__ gg, const float* __restrict__ beg,
                        const float* __restrict__ gh, const float* __restrict__ beh,
                        float* __restrict__ scfg, float* __restrict__ bifg,
                        float* __restrict__ sch,  float* __restrict__ bih) {
    int bid = blockIdx.x;
    const float* base; int C, c; float gv, bev; float *scp, *bip;
    if (bid < 64) {
        base = PFG; C = 64; c = bid;
        gv  = (c < 32) ? gf[c]  : gg[c-32];
        bev = (c < 32) ? bef[c] : beg[c-32];
        scp = scfg; bip = bifg;
    } else {
        base = Ph; C = 130; c = bid - 64;
        gv = gh[c]; bev = beh[c];
        scp = sch; bip = bih;
    }
    int tid = threadIdx.x;
    float s1 = 0.f, s2 = 0.f;
    for (int b = 0; b < B; b++) {
        const float* p = base + ((size_t)b*C + c) * MPT;
        for (int m = tid; m < MPT; m += 256) { float v = p[m]; s1 += v; s2 += v*v; }
    }
    __shared__ float r1[256], r2[256];
    r1[tid] = s1; r2[tid] = s2;
    __syncthreads();
    for (int s = 128; s > 0; s >>= 1) {
        if (tid < s) { r1[tid] += r1[tid+s]; r2[tid] += r2[tid+s]; }
        __syncthreads();
    }
    if (tid == 0) {
        const float invCnt = 1.f / (float)(B * MPT);
        float m = r1[0] * invCnt;
        float var = r2[0] * invCnt - m * m;
        float a = gv * rsqrtf(var + EPS_BN);
        scp[c] = a; bip[c] = bev - m * a;
    }
}

__global__ void norm_relu_fused_kernel(const float* __restrict__ PFG, const float* __restrict__ Ph,
                                       const float* __restrict__ scfg, const float* __restrict__ bifg,
                                       const float* __restrict__ sch,  const float* __restrict__ bih,
                                       float* __restrict__ FG, float* __restrict__ HnB) {
    size_t idx = (size_t)blockIdx.x * 256 + threadIdx.x;
    size_t t1 = (size_t)B * 64 * MPT;
    size_t t2 = (size_t)B * 130 * MPT;
    if (idx < t1) {
        int c = (int)((idx / MPT) % 64);
        FG[idx] = fmaxf(0.f, PFG[idx] * scfg[c] + bifg[c]);
    } else if (idx < t1 + t2) {
        size_t j = idx - t1;
        int c = (int)((j / MPT) % 130);
        HnB[j] = fmaxf(0.f, Ph[j] * sch[c] + bih[c]);
    }
}

// ---------------------------------------------------------------------------
// 8. Attention pass 1 (R6 core): 16 rows/block; F,G from FG buffer.
// ---------------------------------------------------------------------------
__global__ __launch_bounds__(256)
void att_pass1_kernel(const float* __restrict__ FG,
                      float* __restrict__ rmax, float* __restrict__ rinv) {
    int b = blockIdx.y;
    int n0 = blockIdx.x * 16;
    const float* F = FG + (size_t)b * 64 * MPT;
    const float* G = F + (size_t)32 * MPT;
    __shared__ u64 Gs2[16][17];
    __shared__ float smx[16][256];
    __shared__ float ssm[16][256];
    int tid = threadIdx.x;
    {
        int cp = tid >> 4, r = tid & 15;
        float g0 = G[(size_t)(2*cp) * MPT + n0 + r];
        float g1 = G[(size_t)(2*cp + 1) * MPT + n0 + r];
        Gs2[cp][r] = pack2(g0, g1);
    }
    __syncthreads();
    float mx[16], sm[16];
    #pragma unroll
    for (int r = 0; r < 16; r++) { mx[r] = -INFINITY; sm[r] = 0.f; }
    for (int j = 0; j < 16; j++) {
        int m = tid + j * 256;
        u64 fp2[16];
        #pragma unroll
        for (int cp = 0; cp < 16; cp++) {
            float f0 = F[(size_t)(2*cp) * MPT + m];
            float f1 = F[(size_t)(2*cp + 1) * MPT + m];
            fp2[cp] = pack2(f0, f1);
        }
        #pragma unroll
        for (int r = 0; r < 16; r++) {
            u64 sacc = 0;
            #pragma unroll
            for (int cp = 0; cp < 16; cp++) sacc = fma2(fp2[cp], Gs2[cp][r], sacc);
            float s0, s1v; unpack2(sacc, s0, s1v);
            float s = s0 + s1v;
            if (s > mx[r]) { sm[r] = sm[r] * __expf(mx[r] - s) + 1.f; mx[r] = s; }
            else           { sm[r] += __expf(s - mx[r]); }
        }
    }
    #pragma unroll
    for (int r = 0; r < 16; r++) { smx[r][tid] = mx[r]; ssm[r][tid] = sm[r]; }
    __syncthreads();
    int w = tid >> 5, lane = tid & 31;
    for (int rr = w; rr < 16; rr += 8) {
        float M = -INFINITY, S = 0.f;
        for (int e = lane; e < 256; e += 32) {
            float m2 = smx[rr][e], s2 = ssm[rr][e];
            if (m2 > M) { S = S * __expf(M - m2) + s2; M = m2; }
            else        { S += s2 * __expf(m2 - M); }
        }
        #pragma unroll
        for (int o = 16; o > 0; o >>= 1) {
            float m2 = __shfl_xor_sync(0xffffffffu, M, o);
            float s2 = __shfl_xor_sync(0xffffffffu, S, o);
            if (m2 > M) { S = S * __expf(M - m2) + s2; M = m2; }
            else        { S += s2 * __expf(m2 - M); }
        }
        if (lane == 0) {
            rmax[(size_t)b*MPT + n0 + rr] = M;
            rinv[(size_t)b*MPT + n0 + rr] = __fdiv_rn(1.f, S);
        }
    }
}

// ---------------------------------------------------------------------------
// 9. Attention pass 2 v4: m-tile 64, lane owns 2 m (acc2[17] = 34 regs),
//    grid 256 blocks, 2 blocks/SM resident (smem 57KB, regs ~<100).
//    Same per-(c,m) sequential-nt FMA chain -> bit-identical output.
// ---------------------------------------------------------------------------
constexpr int P2_SMEM = 136*33*8 + 32*66*4 + 32*66*4 + 32*33*4 + 32*4;

__global__ __launch_bounds__(256, 2)
void att_pass2_kernel(const float* __restrict__ FG, const float* __restrict__ Hn,
                      const float* __restrict__ rmax, const float* __restrict__ rinv,
                      const float* __restrict__ net, const float* __restrict__ gamma,
                      float* __restrict__ net2) {
    extern __shared__ char smem_raw[];
    u64*   Hs2 = reinterpret_cast<u64*>(smem_raw);       // [136][33] dup(h*rinv)
    float* Fs  = reinterpret_cast<float*>(Hs2 + 136*33); // [32][66]: 64 m
    float* es  = Fs + 32*66;                             // [32][66]
    float* Gs  = es + 32*66;                             // [32][33]
    float* rmx = Gs + 32*33;                             // [32]

    int b = blockIdx.y;
    int m0 = blockIdx.x * 64;
    int tid = threadIdx.x;
    int w = tid >> 5, lane = tid & 31;
    int c0 = w * 17;
    const float* F = FG + (size_t)b * 64 * MPT;
    const float* G = F + (size_t)32 * MPT;

    for (int idx = tid; idx < 32*64; idx += 256) {
        int c = idx >> 6, mm = idx & 63;
        Fs[c*66 + mm] = F[(size_t)c * MPT + m0 + mm];
    }
    u64 acc2[17];
    #pragma unroll
    for (int i = 0; i < 17; i++) acc2[i] = 0;

    for (int nt = 0; nt < 128; nt++) {
        int n0v = nt * 32;
        __syncthreads();
        if (tid < 32) rmx[tid] = rmax[(size_t)b*MPT + n0v + tid];
        for (int idx = tid; idx < 32*32; idx += 256) {
            int c = idx >> 5, jj = idx & 31;
            Gs[c*33 + jj] = G[(size_t)c * MPT + n0v + jj];
        }
        for (int idx = tid; idx < 136*32; idx += 256) {
            int c = idx >> 5, jj = idx & 31;
            float h = 0.f;
            if (c < 130)
                h = Hn[((size_t)b*130 + c) * MPT + n0v + jj] * rinv[(size_t)b*MPT + n0v + jj];
            Hs2[c*33 + jj] = dup2(h);
        }
        __syncthreads();
        // s-phase: thread (nl, mg) computes exp(s - rmax) for 8 m as 4 pairs
        {
            int nl = tid & 31, mg = tid >> 5;
            float gc[32];
            #pragma unroll
            for (int c = 0; c < 32; c++) gc[c] = Gs[c*33 + nl];
            float rm = rmx[nl];
            #pragma unroll
            for (int q = 0; q < 4; q++) {
                int mm = mg*8 + 2*q;
                u64 sacc = 0;
                #pragma unroll
                for (int c = 0; c < 32; c++)
                    sacc = fma2(dup2(gc[c]), *reinterpret_cast<const u64*>(&Fs[c*66 + mm]), sacc);
                float s0, s1v; unpack2(sacc, s0, s1v);
                es[nl*66 + mm]     = __expf(s0 - rm);
                es[nl*66 + mm + 1] = __expf(s1v - rm);
            }
        }
        __syncthreads();
        // o-phase: 17 channels x 2 m per thread
        #pragma unroll 4
        for (int j = 0; j < 32; j++) {
            u64 e01 = *reinterpret_cast<const u64*>(&es[j*66 + 2*lane]);
            #pragma unroll
            for (int i = 0; i < 17; i++)
                acc2[i] = fma2(Hs2[(c0 + i)*33 + j], e01, acc2[i]);
        }
    }
    float gm = gamma[0];
    #pragma unroll
    for (int i = 0; i < 17; i++) {
        int c = c0 + i;
        if (c >= 130) break;
        size_t off = ((size_t)b*130 + c) * MPT + m0 + 2*lane;
        float a0, a1;
        unpack2(acc2[i], a0, a1);
        float2 nv = *reinterpret_cast<const float2*>(&net[off]);
        float2 o2 = make_float2(gm*a0 + nv.x, gm*a1 + nv.y);
        *reinterpret_cast<float2*>(&net2[off]) = o2;
    }
}

// ---------------------------------------------------------------------------
// Host launch
// ---------------------------------------------------------------------------
extern "C" void kernel_launch(void* const* d_in, const int* in_sizes, int n_in,
                              void* d_out, int out_size) {
    float* buf = nullptr; int* ibuf = nullptr; int* candb = nullptr; double* dbuf = nullptr;
    cudaGetSymbolAddress((void**)&buf,   g_buf);
    cudaGetSymbolAddress((void**)&ibuf,  g_ibuf);
    cudaGetSymbolAddress((void**)&candb, g_cand);
    cudaGetSymbolAddress((void**)&dbuf,  g_dbuf);
    cudaFuncSetAttribute(att_pass2_kernel, cudaFuncAttributeMaxDynamicSharedMemorySize, P2_SMEM);

    const float* inp  = (const float*)d_in[0];
    const float* Wa   = (const float*)d_in[1];
    const float* gna  = (const float*)d_in[2];
    const float* bta  = (const float*)d_in[3];
    const float* Wb   = (const float*)d_in[4];
    const float* gnb  = (const float*)d_in[5];
    const float* btb  = (const float*)d_in[6];
    const float* Wf   = (const float*)d_in[7];
    const float* gf   = (const float*)d_in[9];
    const float* bef  = (const float*)d_in[10];
    const float* Wg   = (const float*)d_in[11];
    const float* gg   = (const float*)d_in[13];
    const float* beg  = (const float*)d_in[14];
    const float* Wh   = (const float*)d_in[15];
    const float* gh   = (const float*)d_in[17];
    const float* beh  = (const float*)d_in[18];
    const float* gamma= (const float*)d_in[19];
    const float* W1   = (const float*)d_in[20];
    const float* b1   = (const float*)d_in[21];
    const float* W2   = (const float*)d_in[22];
    const float* b2   = (const float*)d_in[23];
    float* out = (float*)d_out;

    float *xn   = buf + O_XN,   *xnT  = buf + O_XNT, *xTr = buf + O_XTR, *sq = buf + O_SQ;
    float *dot  = buf + O_DOT;
    float *W1AB = buf + O_W1AB, *W2A  = buf + O_W2A, *W2B = buf + O_W2B, *WFG = buf + O_WFG;
    float *U    = buf + O_U;
    float *MxA  = buf + O_MXA,  *MxB  = buf + O_MXB;
    float *partA= buf + O_PARTA,*partB= buf + O_PARTB;
    float *aA   = buf + O_AA,   *cA   = buf + O_CA,  *aB  = buf + O_AB2, *cB = buf + O_CB2;
    float *net  = buf + O_NET;
    float *PFG  = buf + O_PFG,  *Ph   = buf + O_PH;
    float *FG   = buf + O_FG,   *HnB  = buf + O_HN;
    float *scfg = buf + O_SCFG, *bifg = buf + O_BIFG;
    float *sch  = buf + O_SCH,  *bih  = buf + O_BIH;
    float *rmax = buf + O_RMAX, *rinv = buf + O_RINV;
    float *net2 = buf + O_NET2, *y1   = buf + O_Y1;
    double *xnd = dbuf;
    double *sqd = dbuf + (size_t)B*NPT*CIN;

    prep_w_kernel<<<545, 256>>>(Wa, Wb, Wf, Wg, W1AB, W2A, W2B, WFG);
    normalize_kernel<<<(B*NPT*32)/256, 256>>>(inp, xn, xnT, xTr, sq, xnd, sqd);
    gemm_kernel<<<dim3(NPT/64, 8, B), 256>>>(W1AB, 0, inp, nullptr, U, 512, CIN, NPT, 0);
    gemm_kernel<<<dim3(NPT/64, NPT/64, B), 256>>>(xnT, (size_t)NPT*CIN, xn, nullptr, dot, NPT, CIN, NPT, 0);
    topk_cand_kernel<<<(B*NPT)/8, 256>>>(dot, sq, candb);
    refine_topk_kernel<<<B*NPT, 128>>>(xnd, sqd, candb, ibuf);
    edge_fused_kernel<<<dim3(16, 4, B), 256>>>(W2A, U, 0,   xTr, ibuf, 1, MxA, partA);
    edge_fused_kernel<<<dim3(16, 4, B), 256>>>(W2B, U, 256, xTr, ibuf, 2, MxB, partB);
    finalize_edge_kernel<<<1, 512>>>(partA, partB, gna, bta, gnb, btb, aA, cA, aB, cB);
    build_net_kernel<<<(unsigned)(((size_t)B*130*MPT + 255)/256), 256>>>(MxA, MxB, aA, cA, aB, cB, net);
    gemm_kernel<<<dim3(MPT/64, 1, B), 256>>>(WFG, 0, net, nullptr, PFG, 64, 130, MPT, 0);
    gemm_kernel<<<dim3(MPT/64, 3, B), 256>>>(Wh, 0, net, nullptr, Ph, 130, 130, MPT, 0);
    stats_fused_kernel<<<194, 256>>>(PFG, Ph, gf, bef, gg, beg, gh, beh, scfg, bifg, sch, bih);
    {
        size_t tot = (size_t)B*64*MPT + (size_t)B*130*MPT;
        norm_relu_fused_kernel<<<(unsigned)((tot + 255)/256), 256>>>(PFG, Ph, scfg, bifg, sch, bih, FG, HnB);
    }
    att_pass1_kernel<<<dim3(MPT/16, B), 256>>>(FG, rmax, rinv);
    att_pass2_kernel<<<dim3(MPT/64, B), 256, P2_SMEM>>>(FG, HnB, rmax, rinv, net, gamma, net2);
    gemm_kernel<<<dim3(MPT/64, 4, B), 256>>>(W1, 0, net2, b1, y1, 256, 130, MPT, 1);
    gemm_kernel<<<dim3(MPT/64, 2, B), 256>>>(W2, 0, y1, b2, out, 128, 256, MPT, 1);
}

// round 16
// speedup vs baseline: 1.3998x; 1.0240x over previous
#include <cuda_runtime.h>
#include <cstdint>
#include <cstddef>

// ---------------------------------------------------------------------------
// Problem constants
// ---------------------------------------------------------------------------
constexpr int B    = 4;
constexpr int CIN  = 128;
constexpr int NPT  = 1024;   // points
constexpr int KNN  = 9;
constexpr int MPT  = 4096;   // upsampled points = 4*N
constexpr int NCAND = 24;    // fp32 candidate shortlist size
constexpr float EPS_BN = 1e-5f;

// ---------------------------------------------------------------------------
// f32x2 packed-FMA helpers
// ---------------------------------------------------------------------------
using u64 = unsigned long long;
__device__ __forceinline__ u64 dup2(float v) {
    u64 r; asm("mov.b64 %0, {%1, %1};" : "=l"(r) : "f"(v)); return r;
}
__device__ __forceinline__ u64 pack2(float a, float b) {
    u64 r; asm("mov.b64 %0, {%1, %2};" : "=l"(r) : "f"(a), "f"(b)); return r;
}
__device__ __forceinline__ u64 fma2(u64 a, u64 b, u64 c) {
    u64 d; asm("fma.rn.f32x2 %0, %1, %2, %3;" : "=l"(d) : "l"(a), "l"(b), "l"(c)); return d;
}
__device__ __forceinline__ void unpack2(u64 v, float& lo, float& hi) {
    asm("mov.b64 {%0, %1}, %2;" : "=f"(lo), "=f"(hi) : "l"(v));
}

// ---------------------------------------------------------------------------
// Scratch buffer offsets (floats)
// ---------------------------------------------------------------------------
constexpr size_t SZ_XN   = (size_t)B*CIN*NPT;
constexpr size_t SZ_SQ   = (size_t)B*NPT;
constexpr size_t SZ_DOT  = (size_t)B*NPT*NPT;
constexpr size_t SZ_U    = (size_t)B*512*NPT;
constexpr size_t SZ_UV   = (size_t)B*256*NPT;
constexpr size_t SZ_PART = 256*64*2;
constexpr size_t SZ_NET  = (size_t)B*130*MPT;
constexpr size_t SZ_PFG  = (size_t)B*64*MPT;
constexpr size_t SZ_ROW  = (size_t)B*MPT;
constexpr size_t SZ_Y1   = (size_t)B*256*MPT;

constexpr size_t O_XN    = 0;
constexpr size_t O_XNT   = O_XN   + SZ_XN;
constexpr size_t O_XTR   = O_XNT  + SZ_XN;
constexpr size_t O_SQ    = O_XTR  + SZ_XN;
constexpr size_t O_DOT   = O_SQ   + SZ_SQ;
constexpr size_t O_W1AB  = O_DOT  + SZ_DOT;            // [512][128]
constexpr size_t O_W2A   = O_W1AB + 512*128;
constexpr size_t O_W2B   = O_W2A  + 256*128;
constexpr size_t O_WFG   = O_W2B  + 256*128;           // [64][130]
constexpr size_t O_U     = O_WFG  + 64*130;            // [B][512][NPT]
constexpr size_t O_MXA   = O_U    + SZ_U;
constexpr size_t O_MXB   = O_MXA  + SZ_UV;
constexpr size_t O_PARTA = O_MXB  + SZ_UV;
constexpr size_t O_PARTB = O_PARTA+ SZ_PART;
constexpr size_t O_AA    = O_PARTB+ SZ_PART;
constexpr size_t O_CA    = O_AA   + 256;
constexpr size_t O_AB2   = O_CA   + 256;
constexpr size_t O_CB2   = O_AB2  + 256;
constexpr size_t O_NET   = O_CB2  + 256;
constexpr size_t O_PFG   = O_NET  + SZ_NET;            // [B][64][MPT]
constexpr size_t O_PH    = O_PFG  + SZ_PFG;            // [B][130][MPT]
constexpr size_t O_FG    = O_PH   + SZ_NET;            // [B][64][MPT]
constexpr size_t O_HN    = O_FG   + SZ_PFG;            // [B][130][MPT]
constexpr size_t O_SCFG  = O_HN   + SZ_NET;
constexpr size_t O_BIFG  = O_SCFG + 64;
constexpr size_t O_SCH   = O_BIFG + 64;
constexpr size_t O_BIH   = O_SCH  + 130;
constexpr size_t O_RMAX  = O_BIH  + 130;
constexpr size_t O_RINV  = O_RMAX + SZ_ROW;
constexpr size_t O_NET2  = O_RINV + SZ_ROW;
constexpr size_t O_Y1    = O_NET2 + SZ_NET;
constexpr size_t O_END   = O_Y1   + SZ_Y1;

__device__ float  g_buf[O_END];
__device__ int    g_ibuf[(size_t)B*NPT*18];
__device__ int    g_cand[(size_t)B*NPT*NCAND];
__device__ double g_dbuf[(size_t)B*NPT*CIN + (size_t)B*NPT];

// ---------------------------------------------------------------------------
// 0. Weight prep: W1AB=[Wa1;Wb1] (512x128), W2A/W2B (256x128), WFG=[Wf;Wg]
// ---------------------------------------------------------------------------
__global__ void prep_w_kernel(const float* __restrict__ Wa, const float* __restrict__ Wb,
                              const float* __restrict__ Wf, const float* __restrict__ Wg,
                              float* W1AB, float* W2A, float* W2B, float* WFG) {
    int idx = blockIdx.x * 256 + threadIdx.x;
    if (idx < 65536) {
        int o = idx >> 7, c = idx & 127;
        W1AB[idx] = (o < 256) ? Wa[o*256 + c] : Wb[(o-256)*256 + c];
    } else if (idx < 98304) {
        int j = idx - 65536; int o = j >> 7, c = j & 127;
        W2A[j] = Wa[o*256 + 128 + c];
    } else if (idx < 131072) {
        int j = idx - 98304; int o = j >> 7, c = j & 127;
        W2B[j] = Wb[o*256 + 128 + c];
    } else if (idx < 131072 + 64*130) {
        int j = idx - 131072;
        WFG[j] = (j < 32*130) ? Wf[j] : Wg[j - 32*130];
    }
}

// ---------------------------------------------------------------------------
// 1. Normalize in DOUBLE, warp-per-point
// ---------------------------------------------------------------------------
__global__ __launch_bounds__(256)
void normalize_kernel(const float* __restrict__ x,
                      float* __restrict__ xn, float* __restrict__ xnT,
                      float* __restrict__ xTr, float* __restrict__ sq,
                      double* __restrict__ xnd, double* __restrict__ sqd) {
    int gw = (blockIdx.x * 256 + threadIdx.x) >> 5;
    if (gw >= B * NPT) return;
    int lane = threadIdx.x & 31;
    int b = gw >> 10, n = gw & 1023;
    const float* xp = x + (size_t)b * CIN * NPT + n;
    float vf[4];
    double ss = 0.0;
    #pragma unroll
    for (int i = 0; i < 4; i++) {
        float v = xp[(size_t)(i*32 + lane) * NPT];
        vf[i] = v;
        ss += (double)v * (double)v;
    }
    #pragma unroll
    for (int off = 16; off > 0; off >>= 1)
        ss += __shfl_xor_sync(0xffffffffu, ss, off);
    double nrm = sqrt(ss); if (nrm < 1e-12) nrm = 1e-12;
    double inv = 1.0 / nrm;
    double s2 = 0.0;
    #pragma unroll
    for (int i = 0; i < 4; i++) {
        int c = i*32 + lane;
        double v = (double)vf[i] * inv;
        xn[((size_t)b*CIN + c) * NPT + n] = (float)v;
        xnT[((size_t)b*NPT + n) * CIN + c] = (float)v;
        xTr[((size_t)b*NPT + n) * CIN + c] = vf[i];
        xnd[((size_t)b*NPT + n) * CIN + c] = v;
        s2 += v * v;
    }
    #pragma unroll
    for (int off = 16; off > 0; off >>= 1)
        s2 += __shfl_xor_sync(0xffffffffu, s2, off);
    if (lane == 0) { sq[gw] = (float)s2; sqd[gw] = s2; }
}

// ---------------------------------------------------------------------------
// 2. Tiled GEMM v2: 64x64 block, 4m x 4n per thread
// ---------------------------------------------------------------------------
__global__ __launch_bounds__(256)
void gemm_kernel(const float* __restrict__ A, size_t aStride,
                 const float* __restrict__ X, const float* __restrict__ bias,
                 float* __restrict__ C, int M, int K, int Nn, int doRelu) {
    __shared__ float As[32][68];   // [k][m]
    __shared__ float Xs[32][68];   // [k][n]
    int b = blockIdx.z;
    const float* Ab = A + (size_t)b * aStride;
    const float* Xb = X + (size_t)b * K * Nn;
    float* Cb = C + (size_t)b * M * Nn;
    int m0 = blockIdx.y * 64, n0 = blockIdx.x * 64;
    int tid = threadIdx.x;
    int tn = tid & 15, tm = tid >> 4;
    u64 acc[4][2] = {};
    int kTiles = (K + 31) / 32;
    for (int kt = 0; kt < kTiles; kt++) {
        int k0 = kt * 32;
        for (int i = tid; i < 64*32; i += 256) {
            int m = i >> 5, k = i & 31;
            float v = 0.f;
            if (m0 + m < M && k0 + k < K) v = Ab[(size_t)(m0+m)*K + k0 + k];
            As[k][m] = v;
        }
        for (int i = tid; i < 32*64; i += 256) {
            int k = i >> 6, n = i & 63;
            float v = 0.f;
            if (k0 + k < K) v = Xb[(size_t)(k0+k)*Nn + n0 + n];
            Xs[k][n] = v;
        }
        __syncthreads();
        #pragma unroll
        for (int kk = 0; kk < 32; kk++) {
            float4 a4 = *reinterpret_cast<const float4*>(&As[kk][tm*4]);
            u64 x0 = *reinterpret_cast<const u64*>(&Xs[kk][tn*4]);
            u64 x1 = *reinterpret_cast<const u64*>(&Xs[kk][tn*4 + 2]);
            u64 a0 = dup2(a4.x), a1 = dup2(a4.y), a2 = dup2(a4.z), a3 = dup2(a4.w);
            acc[0][0] = fma2(a0, x0, acc[0][0]); acc[0][1] = fma2(a0, x1, acc[0][1]);
            acc[1][0] = fma2(a1, x0, acc[1][0]); acc[1][1] = fma2(a1, x1, acc[1][1]);
            acc[2][0] = fma2(a2, x0, acc[2][0]); acc[2][1] = fma2(a2, x1, acc[2][1]);
            acc[3][0] = fma2(a3, x0, acc[3][0]); acc[3][1] = fma2(a3, x1, acc[3][1]);
        }
        __syncthreads();
    }
    #pragma unroll
    for (int mi = 0; mi < 4; mi++) {
        int m = m0 + tm*4 + mi;
        if (m >= M) continue;
        float bv = bias ? bias[m] : 0.f;
        float4 o4;
        unpack2(acc[mi][0], o4.x, o4.y);
        unpack2(acc[mi][1], o4.z, o4.w);
        o4.x += bv; o4.y += bv; o4.z += bv; o4.w += bv;
        if (doRelu) {
            o4.x = fmaxf(o4.x, 0.f); o4.y = fmaxf(o4.y, 0.f);
            o4.z = fmaxf(o4.z, 0.f); o4.w = fmaxf(o4.w, 0.f);
        }
        *reinterpret_cast<float4*>(&Cb[(size_t)m*Nn + n0 + tn*4]) = o4;
    }
}

// ---------------------------------------------------------------------------
// 3a. Candidate top-24, warp-per-row
// ---------------------------------------------------------------------------
__global__ __launch_bounds__(256)
void topk_cand_kernel(const float* __restrict__ dot, const float* __restrict__ sq,
                      int* __restrict__ candout) {
    int warp = threadIdx.x >> 5, lane = threadIdx.x & 31;
    int bn = blockIdx.x * 8 + warp;
    int b = bn >> 10;
    const float* drow = dot + (size_t)bn * 1024;
    const float* sqb = sq + b * 1024;
    float sqn = sqb[bn & 1023];
    float val[32];
    #pragma unroll
    for (int q = 0; q < 32; q++) {
        int m = q * 32 + lane;
        float t1 = __fadd_rn(sqn, -__fmul_rn(2.f, drow[m]));
        val[q] = -__fadd_rn(t1, sqb[m]);
    }
    float bv = val[0]; int bq = 0;
    #pragma unroll
    for (int q = 1; q < 32; q++) if (val[q] > bv) { bv = val[q]; bq = q; }
    for (int it = 0; it < NCAND; it++) {
        float v = bv; int bi = bq * 32 + lane;
        #pragma unroll
        for (int off = 16; off > 0; off >>= 1) {
            float v2 = __shfl_xor_sync(0xffffffffu, v, off);
            int   i2 = __shfl_xor_sync(0xffffffffu, bi, off);
            if (v2 > v || (v2 == v && i2 < bi)) { v = v2; bi = i2; }
        }
        if (lane == 0) candout[(size_t)bn*NCAND + it] = bi;
        if ((bi & 31) == lane) {
            int qs = bi >> 5;
            #pragma unroll
            for (int q = 0; q < 32; q++) if (q == qs) val[q] = -INFINITY;
            bv = val[0]; bq = 0;
            #pragma unroll
            for (int q = 1; q < 32; q++) if (val[q] > bv) { bv = val[q]; bq = q; }
        }
    }
}

// ---------------------------------------------------------------------------
// 3b. Refine: exact double dists, fp32-round, stable sort, top-18
// ---------------------------------------------------------------------------
__global__ __launch_bounds__(128)
void refine_topk_kernel(const double* __restrict__ xnd, const double* __restrict__ sqd,
                        const int* __restrict__ cand, int* __restrict__ idxout) {
    int bn = blockIdx.x;
    int b = bn >> 10;
    int tid = threadIdx.x, lane = tid & 31, warp = tid >> 5;
    __shared__ float scores[NCAND];
    __shared__ int   cidx[NCAND];
    if (tid < NCAND) cidx[tid] = cand[(size_t)bn*NCAND + tid];
    const double* xrp = xnd + (size_t)bn * 128 + lane * 4;
    double xr0 = xrp[0], xr1 = xrp[1], xr2 = xrp[2], xr3 = xrp[3];
    __syncthreads();
    double sqn = sqd[bn];
    for (int k = warp; k < NCAND; k += 4) {
        int m = cidx[k];
        const double* xm = xnd + ((size_t)b*NPT + m) * 128 + lane * 4;
        double s = xr0*xm[0] + xr1*xm[1] + xr2*xm[2] + xr3*xm[3];
        #pragma unroll
        for (int off = 16; off > 0; off >>= 1)
            s += __shfl_xor_sync(0xffffffffu, s, off);
        if (lane == 0)
            scores[k] = (float)(-(sqn - 2.0 * s + sqd[(size_t)b*NPT + m]));
    }
    __syncthreads();
    if (tid == 0) {
        float sc[NCAND]; int ci[NCAND];
        for (int i = 0; i < NCAND; i++) { sc[i] = scores[i]; ci[i] = cidx[i]; }
        for (int i = 1; i < NCAND; i++) {
            float sv = sc[i]; int iv = ci[i];
            int j = i - 1;
            while (j >= 0 && (sc[j] < sv || (sc[j] == sv && ci[j] > iv))) {
                sc[j+1] = sc[j]; ci[j+1] = ci[j]; j--;
            }
            sc[j+1] = sv; ci[j+1] = iv;
        }
        for (int r = 0; r < 18; r++) idxout[(size_t)bn*18 + r] = ci[r];
    }
}

// ---------------------------------------------------------------------------
// 4. FUSED edge conv v2: 64o x 64n block, 4x4 thread tile
// ---------------------------------------------------------------------------
__global__ __launch_bounds__(256)
void edge_fused_kernel(const float* __restrict__ W2, const float* __restrict__ u,
                       int uoff, const float* __restrict__ xT, const int* __restrict__ ibuf,
                       int step, float* __restrict__ Mx, float* __restrict__ part) {
    __shared__ float W2s[128][68];  // [k][m-64]
    __shared__ float Xs[32][68];    // [k][n]
    __shared__ int   js[64];
    int b = blockIdx.z, bx = blockIdx.x;
    int m0 = blockIdx.y * 64, n0 = bx * 64;
    int tid = threadIdx.x;
    int tn = tid & 15, tm = tid >> 4;
    const float* xTb = xT + (size_t)b * NPT * CIN;

    for (int i = tid; i < 64*128; i += 256) {
        int m = i >> 7, k = i & 127;
        W2s[k][m] = W2[(size_t)(m0+m)*128 + k];
    }
    float4 u4[4];
    #pragma unroll
    for (int mi = 0; mi < 4; mi++)
        u4[mi] = *reinterpret_cast<const float4*>(
            &u[((size_t)b*512 + uoff + m0 + tm*4 + mi)*NPT + n0 + tn*4]);

    float mx[4][4], s1[4] = {0,0,0,0}, s2s[4] = {0,0,0,0};
    #pragma unroll
    for (int mi = 0; mi < 4; mi++)
        #pragma unroll
        for (int q = 0; q < 4; q++) mx[mi][q] = -INFINITY;
    __syncthreads();

    for (int k = 0; k < 9; k++) {
        if (tid < 64) js[tid] = ibuf[((size_t)b*NPT + n0 + tid)*18 + k*step];
        u64 acc[4][2] = {};
        #pragma unroll
        for (int ct = 0; ct < 4; ct++) {
            __syncthreads();
            for (int i = tid; i < 32*64; i += 256) {
                int c = i & 31, n = i >> 5;
                float xj = xTb[(size_t)js[n]*128 + ct*32 + c];
                float xi = xTb[(size_t)(n0 + n)*128 + ct*32 + c];
                Xs[c][n] = __fadd_rn(xj, -xi);
            }
            __syncthreads();
            #pragma unroll
            for (int kk = 0; kk < 32; kk++) {
                float4 a4 = *reinterpret_cast<const float4*>(&W2s[ct*32+kk][tm*4]);
                u64 x0 = *reinterpret_cast<const u64*>(&Xs[kk][tn*4]);
                u64 x1 = *reinterpret_cast<const u64*>(&Xs[kk][tn*4 + 2]);
                u64 a0 = dup2(a4.x), a1 = dup2(a4.y), a2 = dup2(a4.z), a3 = dup2(a4.w);
                acc[0][0] = fma2(a0, x0, acc[0][0]); acc[0][1] = fma2(a0, x1, acc[0][1]);
                acc[1][0] = fma2(a1, x0, acc[1][0]); acc[1][1] = fma2(a1, x1, acc[1][1]);
                acc[2][0] = fma2(a2, x0, acc[2][0]); acc[2][1] = fma2(a2, x1, acc[2][1]);
                acc[3][0] = fma2(a3, x0, acc[3][0]); acc[3][1] = fma2(a3, x1, acc[3][1]);
            }
        }
        #pragma unroll
        for (int mi = 0; mi < 4; mi++) {
            float d0, d1, d2, d3;
            unpack2(acc[mi][0], d0, d1);
            unpack2(acc[mi][1], d2, d3);
            float z0 = u4[mi].x + d0, z1 = u4[mi].y + d1;
            float z2 = u4[mi].z + d2, z3 = u4[mi].w + d3;
            mx[mi][0] = fmaxf(mx[mi][0], z0); mx[mi][1] = fmaxf(mx[mi][1], z1);
            mx[mi][2] = fmaxf(mx[mi][2], z2); mx[mi][3] = fmaxf(mx[mi][3], z3);
            s1[mi]  += (z0 + z1) + (z2 + z3);
            s2s[mi] += (z0*z0 + z1*z1) + (z2*z2 + z3*z3);
        }
        __syncthreads();
    }
    #pragma unroll
    for (int mi = 0; mi < 4; mi++) {
        float4 o4 = make_float4(mx[mi][0], mx[mi][1], mx[mi][2], mx[mi][3]);
        *reinterpret_cast<float4*>(
            &Mx[((size_t)b*256 + m0 + tm*4 + mi)*NPT + n0 + tn*4]) = o4;
    }
    #pragma unroll
    for (int mi = 0; mi < 4; mi++) {
        float a = s1[mi], c2 = s2s[mi];
        #pragma unroll
        for (int off = 1; off < 16; off <<= 1) {
            a  += __shfl_xor_sync(0xffffffffu, a, off);
            c2 += __shfl_xor_sync(0xffffffffu, c2, off);
        }
        if (tn == 0) {
            int o = m0 + tm*4 + mi;
            int slot = b*16 + bx;
            part[((size_t)o*64 + slot)*2]     = a;
            part[((size_t)o*64 + slot)*2 + 1] = c2;
        }
    }
}

__global__ void finalize_edge_kernel(const float* __restrict__ partA, const float* __restrict__ partB,
                                     const float* __restrict__ gA, const float* __restrict__ btA,
                                     const float* __restrict__ gB, const float* __restrict__ btB,
                                     float* aA, float* cA, float* aB, float* cB) {
    int t = threadIdx.x;
    const float invCnt = 1.f / (float)(B * NPT * KNN);
    if (t < 256) {
        float s1 = 0.f, s2 = 0.f;
        for (int j = 0; j < 64; j++) { s1 += partA[((size_t)t*64 + j)*2]; s2 += partA[((size_t)t*64 + j)*2 + 1]; }
        float m = s1 * invCnt;
        float var = s2 * invCnt - m * m;
        float a = gA[t] * rsqrtf(var + EPS_BN);
        aA[t] = a; cA[t] = btA[t] - m * a;
    } else {
        int o = t - 256;
        float s1 = 0.f, s2 = 0.f;
        for (int j = 0; j < 64; j++) { s1 += partB[((size_t)o*64 + j)*2]; s2 += partB[((size_t)o*64 + j)*2 + 1]; }
        float m = s1 * invCnt;
        float var = s2 * invCnt - m * m;
        float a = gB[o] * rsqrtf(var + EPS_BN);
        aB[o] = a; cB[o] = btB[o] - m * a;
    }
}

// ---------------------------------------------------------------------------
// 6. Build net — elementwise
// ---------------------------------------------------------------------------
__global__ __launch_bounds__(256)
void build_net_kernel(const float* __restrict__ MxA, const float* __restrict__ MxB,
                      const float* __restrict__ aA, const float* __restrict__ cA,
                      const float* __restrict__ aB, const float* __restrict__ cB,
                      float* __restrict__ net) {
    size_t idx = (size_t)blockIdx.x * 256 + threadIdx.x;
    if (idx >= (size_t)B * 130 * MPT) return;
    int b = (int)(idx / (130 * MPT));
    int r = (int)(idx - (size_t)b * 130 * MPT);
    int c = r >> 12, m = r & 4095;
    float val;
    if (c < 128) {
        int n = m >> 2, j = m & 3;
        if (j < 2) {
            int o = j*128 + c;
            val = fmaxf(0.f, aA[o] * MxA[((size_t)b*256 + o)*NPT + n] + cA[o]);
        } else {
            int o = (j-2)*128 + c;
            val = fmaxf(0.f, aB[o] * MxB[((size_t)b*256 + o)*NPT + n] + cB[o]);
        }
    } else if (c == 128) {
        val = ((m >> 10) < 2) ? -0.2f : 0.2f;
    } else {
        val = ((m >> 10) & 1) ? 0.2f : -0.2f;
    }
    net[idx] = val;
}

// ---------------------------------------------------------------------------
// 7. FUSED attention BN stats (194 blocks) + fused normalize+relu
// ---------------------------------------------------------------------------
__global__ __launch_bounds__(256)
void stats_fused_kernel(const float* __restrict__ PFG, const float* __restrict__ Ph,
                        const float* __restrict__ gf, const float* __restrict__ bef,
                        const float* __restrict__ gg, const float* __restrict__ beg,
                        const float* __restrict__ gh, const float* __restrict__ beh,
                        float* __restrict__ scfg, float* __restrict__ bifg,
                        float* __restrict__ sch,  float* __restrict__ bih) {
    int bid = blockIdx.x;
    const float* base; int C, c; float gv, bev; float *scp, *bip;
    if (bid < 64) {
        base = PFG; C = 64; c = bid;
        gv  = (c < 32) ? gf[c]  : gg[c-32];
        bev = (c < 32) ? bef[c] : beg[c-32];
        scp = scfg; bip = bifg;
    } else {
        base = Ph; C = 130; c = bid - 64;
        gv = gh[c]; bev = beh[c];
        scp = sch; bip = bih;
    }
    int tid = threadIdx.x;
    float s1 = 0.f, s2 = 0.f;
    for (int b = 0; b < B; b++) {
        const float* p = base + ((size_t)b*C + c) * MPT;
        for (int m = tid; m < MPT; m += 256) { float v = p[m]; s1 += v; s2 += v*v; }
    }
    __shared__ float r1[256], r2[256];
    r1[tid] = s1; r2[tid] = s2;
    __syncthreads();
    for (int s = 128; s > 0; s >>= 1) {
        if (tid < s) { r1[tid] += r1[tid+s]; r2[tid] += r2[tid+s]; }
        __syncthreads();
    }
    if (tid == 0) {
        const float invCnt = 1.f / (float)(B * MPT);
        float m = r1[0] * invCnt;
        float var = r2[0] * invCnt - m * m;
        float a = gv * rsqrtf(var + EPS_BN);
        scp[c] = a; bip[c] = bev - m * a;
    }
}

__global__ void norm_relu_fused_kernel(const float* __restrict__ PFG, const float* __restrict__ Ph,
                                       const float* __restrict__ scfg, const float* __restrict__ bifg,
                                       const float* __restrict__ sch,  const float* __restrict__ bih,
                                       float* __restrict__ FG, float* __restrict__ HnB) {
    size_t idx = (size_t)blockIdx.x * 256 + threadIdx.x;
    size_t t1 = (size_t)B * 64 * MPT;
    size_t t2 = (size_t)B * 130 * MPT;
    if (idx < t1) {
        int c = (int)((idx / MPT) % 64);
        FG[idx] = fmaxf(0.f, PFG[idx] * scfg[c] + bifg[c]);
    } else if (idx < t1 + t2) {
        size_t j = idx - t1;
        int c = (int)((j / MPT) % 130);
        HnB[j] = fmaxf(0.f, Ph[j] * sch[c] + bih[c]);
    }
}

// ---------------------------------------------------------------------------
// 8. Attention pass 1 (R6 core): 16 rows/block; F,G from FG buffer.
// ---------------------------------------------------------------------------
__global__ __launch_bounds__(256)
void att_pass1_kernel(const float* __restrict__ FG,
                      float* __restrict__ rmax, float* __restrict__ rinv) {
    int b = blockIdx.y;
    int n0 = blockIdx.x * 16;
    const float* F = FG + (size_t)b * 64 * MPT;
    const float* G = F + (size_t)32 * MPT;
    __shared__ u64 Gs2[16][17];
    __shared__ float smx[16][256];
    __shared__ float ssm[16][256];
    int tid = threadIdx.x;
    {
        int cp = tid >> 4, r = tid & 15;
        float g0 = G[(size_t)(2*cp) * MPT + n0 + r];
        float g1 = G[(size_t)(2*cp + 1) * MPT + n0 + r];
        Gs2[cp][r] = pack2(g0, g1);
    }
    __syncthreads();
    float mx[16], sm[16];
    #pragma unroll
    for (int r = 0; r < 16; r++) { mx[r] = -INFINITY; sm[r] = 0.f; }
    for (int j = 0; j < 16; j++) {
        int m = tid + j * 256;
        u64 fp2[16];
        #pragma unroll
        for (int cp = 0; cp < 16; cp++) {
            float f0 = F[(size_t)(2*cp) * MPT + m];
            float f1 = F[(size_t)(2*cp + 1) * MPT + m];
            fp2[cp] = pack2(f0, f1);
        }
        #pragma unroll
        for (int r = 0; r < 16; r++) {
            u64 sacc = 0;
            #pragma unroll
            for (int cp = 0; cp < 16; cp++) sacc = fma2(fp2[cp], Gs2[cp][r], sacc);
            float s0, s1v; unpack2(sacc, s0, s1v);
            float s = s0 + s1v;
            if (s > mx[r]) { sm[r] = sm[r] * __expf(mx[r] - s) + 1.f; mx[r] = s; }
            else           { sm[r] += __expf(s - mx[r]); }
        }
    }
    #pragma unroll
    for (int r = 0; r < 16; r++) { smx[r][tid] = mx[r]; ssm[r][tid] = sm[r]; }
    __syncthreads();
    int w = tid >> 5, lane = tid & 31;
    for (int rr = w; rr < 16; rr += 8) {
        float M = -INFINITY, S = 0.f;
        for (int e = lane; e < 256; e += 32) {
            float m2 = smx[rr][e], s2 = ssm[rr][e];
            if (m2 > M) { S = S * __expf(M - m2) + s2; M = m2; }
            else        { S += s2 * __expf(m2 - M); }
        }
        #pragma unroll
        for (int o = 16; o > 0; o >>= 1) {
            float m2 = __shfl_xor_sync(0xffffffffu, M, o);
            float s2 = __shfl_xor_sync(0xffffffffu, S, o);
            if (m2 > M) { S = S * __expf(M - m2) + s2; M = m2; }
            else        { S += s2 * __expf(m2 - M); }
        }
        if (lane == 0) {
            rmax[(size_t)b*MPT + n0 + rr] = M;
            rinv[(size_t)b*MPT + n0 + rr] = __fdiv_rn(1.f, S);
        }
    }
}

// ---------------------------------------------------------------------------
// 9. Attention pass 2 v5: 512-thread block, m-tile 128, warp owns 9 channels
//    (acc2[9][2]=36 regs), 16 warps/block = 4 warps/SMSP at 1 block/SM.
//    Same per-(c,m) sequential-nt FMA chain -> bit-identical output.
// ---------------------------------------------------------------------------
constexpr int P2_SMEM = 136*33*8 + 32*130*4 + 32*130*4 + 32*33*4 + 32*4;

__global__ __launch_bounds__(512, 1)
void att_pass2_kernel(const float* __restrict__ FG, const float* __restrict__ Hn,
                      const float* __restrict__ rmax, const float* __restrict__ rinv,
                      const float* __restrict__ net, const float* __restrict__ gamma,
                      float* __restrict__ net2) {
    extern __shared__ char smem_raw[];
    u64*   Hs2 = reinterpret_cast<u64*>(smem_raw);       // [136][33] dup(h*rinv)
    float* Fs  = reinterpret_cast<float*>(Hs2 + 136*33); // [32][130]
    float* es  = Fs + 32*130;                            // [32][130]
    float* Gs  = es + 32*130;                            // [32][33]
    float* rmx = Gs + 32*33;                             // [32]

    int b = blockIdx.y;
    int m0 = blockIdx.x * 128;
    int tid = threadIdx.x;
    int w = tid >> 5, lane = tid & 31;
    int c0 = w * 9;                 // 16 warps x 9 = 144 >= 130
    const float* F = FG + (size_t)b * 64 * MPT;
    const float* G = F + (size_t)32 * MPT;

    for (int idx = tid; idx < 32*128; idx += 512) {
        int c = idx >> 7, mm = idx & 127;
        Fs[c*130 + mm] = F[(size_t)c * MPT + m0 + mm];
    }
    u64 acc2[9][2];
    #pragma unroll
    for (int i = 0; i < 9; i++) { acc2[i][0] = 0; acc2[i][1] = 0; }

    for (int nt = 0; nt < 128; nt++) {
        int n0v = nt * 32;
        __syncthreads();
        if (tid < 32) rmx[tid] = rmax[(size_t)b*MPT + n0v + tid];
        for (int idx = tid; idx < 32*32; idx += 512) {
            int c = idx >> 5, jj = idx & 31;
            Gs[c*33 + jj] = G[(size_t)c * MPT + n0v + jj];
        }
        for (int idx = tid; idx < 136*32; idx += 512) {
            int c = idx >> 5, jj = idx & 31;
            float h = 0.f;
            if (c < 130)
                h = Hn[((size_t)b*130 + c) * MPT + n0v + jj] * rinv[(size_t)b*MPT + n0v + jj];
            Hs2[c*33 + jj] = dup2(h);
        }
        __syncthreads();
        // s-phase: thread (nl, mg) computes exp(s - rmax) for 8 m as 4 pairs
        {
            int nl = tid & 31, mg = tid >> 5;   // mg 0..15
            float gc[32];
            #pragma unroll
            for (int c = 0; c < 32; c++) gc[c] = Gs[c*33 + nl];
            float rm = rmx[nl];
            #pragma unroll
            for (int q = 0; q < 4; q++) {
                int mm = mg*8 + 2*q;
                u64 sacc = 0;
                #pragma unroll
                for (int c = 0; c < 32; c++)
                    sacc = fma2(dup2(gc[c]), *reinterpret_cast<const u64*>(&Fs[c*130 + mm]), sacc);
                float s0, s1v; unpack2(sacc, s0, s1v);
                es[nl*130 + mm]     = __expf(s0 - rm);
                es[nl*130 + mm + 1] = __expf(s1v - rm);
            }
        }
        __syncthreads();
        // o-phase: 9 channels x 4 m per thread
        #pragma unroll 4
        for (int j = 0; j < 32; j++) {
            u64 e01 = *reinterpret_cast<const u64*>(&es[j*130 + 4*lane]);
            u64 e23 = *reinterpret_cast<const u64*>(&es[j*130 + 4*lane + 2]);
            #pragma unroll
            for (int i = 0; i < 9; i++) {
                u64 h2 = Hs2[(c0 + i)*33 + j];
                acc2[i][0] = fma2(h2, e01, acc2[i][0]);
                acc2[i][1] = fma2(h2, e23, acc2[i][1]);
            }
        }
    }
    float gm = gamma[0];
    #pragma unroll
    for (int i = 0; i < 9; i++) {
        int c = c0 + i;
        if (c >= 130) break;
        size_t off = ((size_t)b*130 + c) * MPT + m0 + 4*lane;
        float a0, a1, a2, a3;
        unpack2(acc2[i][0], a0, a1);
        unpack2(acc2[i][1], a2, a3);
        float4 nv = *reinterpret_cast<const float4*>(&net[off]);
        float4 o4 = make_float4(gm*a0 + nv.x, gm*a1 + nv.y, gm*a2 + nv.z, gm*a3 + nv.w);
        *reinterpret_cast<float4*>(&net2[off]) = o4;
    }
}

// ---------------------------------------------------------------------------
// Host launch
// ---------------------------------------------------------------------------
extern "C" void kernel_launch(void* const* d_in, const int* in_sizes, int n_in,
                              void* d_out, int out_size) {
    float* buf = nullptr; int* ibuf = nullptr; int* candb = nullptr; double* dbuf = nullptr;
    cudaGetSymbolAddress((void**)&buf,   g_buf);
    cudaGetSymbolAddress((void**)&ibuf,  g_ibuf);
    cudaGetSymbolAddress((void**)&candb, g_cand);
    cudaGetSymbolAddress((void**)&dbuf,  g_dbuf);
    cudaFuncSetAttribute(att_pass2_kernel, cudaFuncAttributeMaxDynamicSharedMemorySize, P2_SMEM);

    const float* inp  = (const float*)d_in[0];
    const float* Wa   = (const float*)d_in[1];
    const float* gna  = (const float*)d_in[2];
    const float* bta  = (const float*)d_in[3];
    const float* Wb   = (const float*)d_in[4];
    const float* gnb  = (const float*)d_in[5];
    const float* btb  = (const float*)d_in[6];
    const float* Wf   = (const float*)d_in[7];
    const float* gf   = (const float*)d_in[9];
    const float* bef  = (const float*)d_in[10];
    const float* Wg   = (const float*)d_in[11];
    const float* gg   = (const float*)d_in[13];
    const float* beg  = (const float*)d_in[14];
    const float* Wh   = (const float*)d_in[15];
    const float* gh   = (const float*)d_in[17];
    const float* beh  = (const float*)d_in[18];
    const float* gamma= (const float*)d_in[19];
    const float* W1   = (const float*)d_in[20];
    const float* b1   = (const float*)d_in[21];
    const float* W2   = (const float*)d_in[22];
    const float* b2   = (const float*)d_in[23];
    float* out = (float*)d_out;

    float *xn   = buf + O_XN,   *xnT  = buf + O_XNT, *xTr = buf + O_XTR, *sq = buf + O_SQ;
    float *dot  = buf + O_DOT;
    float *W1AB = buf + O_W1AB, *W2A  = buf + O_W2A, *W2B = buf + O_W2B, *WFG = buf + O_WFG;
    float *U    = buf + O_U;
    float *MxA  = buf + O_MXA,  *MxB  = buf + O_MXB;
    float *partA= buf + O_PARTA,*partB= buf + O_PARTB;
    float *aA   = buf + O_AA,   *cA   = buf + O_CA,  *aB  = buf + O_AB2, *cB = buf + O_CB2;
    float *net  = buf + O_NET;
    float *PFG  = buf + O_PFG,  *Ph   = buf + O_PH;
    float *FG   = buf + O_FG,   *HnB  = buf + O_HN;
    float *scfg = buf + O_SCFG, *bifg = buf + O_BIFG;
    float *sch  = buf + O_SCH,  *bih  = buf + O_BIH;
    float *rmax = buf + O_RMAX, *rinv = buf + O_RINV;
    float *net2 = buf + O_NET2, *y1   = buf + O_Y1;
    double *xnd = dbuf;
    double *sqd = dbuf + (size_t)B*NPT*CIN;

    prep_w_kernel<<<545, 256>>>(Wa, Wb, Wf, Wg, W1AB, W2A, W2B, WFG);
    normalize_kernel<<<(B*NPT*32)/256, 256>>>(inp, xn, xnT, xTr, sq, xnd, sqd);
    gemm_kernel<<<dim3(NPT/64, 8, B), 256>>>(W1AB, 0, inp, nullptr, U, 512, CIN, NPT, 0);
    gemm_kernel<<<dim3(NPT/64, NPT/64, B), 256>>>(xnT, (size_t)NPT*CIN, xn, nullptr, dot, NPT, CIN, NPT, 0);
    topk_cand_kernel<<<(B*NPT)/8, 256>>>(dot, sq, candb);
    refine_topk_kernel<<<B*NPT, 128>>>(xnd, sqd, candb, ibuf);
    edge_fused_kernel<<<dim3(16, 4, B), 256>>>(W2A, U, 0,   xTr, ibuf, 1, MxA, partA);
    edge_fused_kernel<<<dim3(16, 4, B), 256>>>(W2B, U, 256, xTr, ibuf, 2, MxB, partB);
    finalize_edge_kernel<<<1, 512>>>(partA, partB, gna, bta, gnb, btb, aA, cA, aB, cB);
    build_net_kernel<<<(unsigned)(((size_t)B*130*MPT + 255)/256), 256>>>(MxA, MxB, aA, cA, aB, cB, net);
    gemm_kernel<<<dim3(MPT/64, 1, B), 256>>>(WFG, 0, net, nullptr, PFG, 64, 130, MPT, 0);
    gemm_kernel<<<dim3(MPT/64, 3, B), 256>>>(Wh, 0, net, nullptr, Ph, 130, 130, MPT, 0);
    stats_fused_kernel<<<194, 256>>>(PFG, Ph, gf, bef, gg, beg, gh, beh, scfg, bifg, sch, bih);
    {
        size_t tot = (size_t)B*64*MPT + (size_t)B*130*MPT;
        norm_relu_fused_kernel<<<(unsigned)((tot + 255)/256), 256>>>(PFG, Ph, scfg, bifg, sch, bih, FG, HnB);
    }
    att_pass1_kernel<<<dim3(MPT/16, B), 256>>>(FG, rmax, rinv);
    att_pass2_kernel<<<dim3(MPT/128, B), 512, P2_SMEM>>>(FG, HnB, rmax, rinv, net, gamma, net2);
    gemm_kernel<<<dim3(MPT/64, 4, B), 256>>>(W1, 0, net2, b1, y1, 256, 130, MPT, 1);
    gemm_kernel<<<dim3(MPT/64, 2, B), 256>>>(W2, 0, y1, b2, out, 128, 256, MPT, 1);
}

// round 17
// speedup vs baseline: 1.6436x; 1.1742x over previous
#include <cuda_runtime.h>
#include <cstdint>
#include <cstddef>

// ---------------------------------------------------------------------------
// Problem constants
// ---------------------------------------------------------------------------
constexpr int B    = 4;
constexpr int CIN  = 128;
constexpr int NPT  = 1024;   // points
constexpr int KNN  = 9;
constexpr int MPT  = 4096;   // upsampled points = 4*N
constexpr int NCAND = 24;    // fp32 candidate shortlist size
constexpr float EPS_BN = 1e-5f;

// ---------------------------------------------------------------------------
// f32x2 packed-FMA helpers
// ---------------------------------------------------------------------------
using u64 = unsigned long long;
__device__ __forceinline__ u64 dup2(float v) {
    u64 r; asm("mov.b64 %0, {%1, %1};" : "=l"(r) : "f"(v)); return r;
}
__device__ __forceinline__ u64 pack2(float a, float b) {
    u64 r; asm("mov.b64 %0, {%1, %2};" : "=l"(r) : "f"(a), "f"(b)); return r;
}
__device__ __forceinline__ u64 fma2(u64 a, u64 b, u64 c) {
    u64 d; asm("fma.rn.f32x2 %0, %1, %2, %3;" : "=l"(d) : "l"(a), "l"(b), "l"(c)); return d;
}
__device__ __forceinline__ void unpack2(u64 v, float& lo, float& hi) {
    asm("mov.b64 {%0, %1}, %2;" : "=f"(lo), "=f"(hi) : "l"(v));
}

// ---------------------------------------------------------------------------
// Scratch buffer offsets (floats)
// ---------------------------------------------------------------------------
constexpr size_t SZ_XN   = (size_t)B*CIN*NPT;
constexpr size_t SZ_SQ   = (size_t)B*NPT;
constexpr size_t SZ_DOT  = (size_t)B*NPT*NPT;
constexpr size_t SZ_U    = (size_t)B*512*NPT;
constexpr size_t SZ_UV   = (size_t)B*256*NPT;
constexpr size_t SZ_PART = 256*64*2;
constexpr size_t SZ_NET  = (size_t)B*130*MPT;
constexpr size_t SZ_PFG  = (size_t)B*64*MPT;
constexpr size_t SZ_ROW  = (size_t)B*MPT;
constexpr size_t SZ_Y1   = (size_t)B*256*MPT;

constexpr size_t O_XN    = 0;
constexpr size_t O_XNT   = O_XN   + SZ_XN;
constexpr size_t O_XTR   = O_XNT  + SZ_XN;
constexpr size_t O_SQ    = O_XTR  + SZ_XN;
constexpr size_t O_DOT   = O_SQ   + SZ_SQ;
constexpr size_t O_W1AB  = O_DOT  + SZ_DOT;            // [512][128]
constexpr size_t O_W2A   = O_W1AB + 512*128;
constexpr size_t O_W2B   = O_W2A  + 256*128;
constexpr size_t O_WFG   = O_W2B  + 256*128;           // [64][130]
constexpr size_t O_U     = O_WFG  + 64*130;            // [B][512][NPT]
constexpr size_t O_MXA   = O_U    + SZ_U;
constexpr size_t O_MXB   = O_MXA  + SZ_UV;
constexpr size_t O_PARTA = O_MXB  + SZ_UV;
constexpr size_t O_PARTB = O_PARTA+ SZ_PART;
constexpr size_t O_AA    = O_PARTB+ SZ_PART;
constexpr size_t O_CA    = O_AA   + 256;
constexpr size_t O_AB2   = O_CA   + 256;
constexpr size_t O_CB2   = O_AB2  + 256;
constexpr size_t O_NET   = O_CB2  + 256;
constexpr size_t O_PFG   = O_NET  + SZ_NET;            // [B][64][MPT]
constexpr size_t O_PH    = O_PFG  + SZ_PFG;            // [B][130][MPT]
constexpr size_t O_FG    = O_PH   + SZ_NET;            // [B][64][MPT]
constexpr size_t O_HN    = O_FG   + SZ_PFG;            // [B][130][MPT]
constexpr size_t O_SCFG  = O_HN   + SZ_NET;
constexpr size_t O_BIFG  = O_SCFG + 64;
constexpr size_t O_SCH   = O_BIFG + 64;
constexpr size_t O_BIH   = O_SCH  + 130;
constexpr size_t O_RMAX  = O_BIH  + 130;
constexpr size_t O_RINV  = O_RMAX + SZ_ROW;
constexpr size_t O_NET2  = O_RINV + SZ_ROW;
constexpr size_t O_Y1    = O_NET2 + SZ_NET;
constexpr size_t O_END   = O_Y1   + SZ_Y1;

__device__ float  g_buf[O_END];
__device__ int    g_ibuf[(size_t)B*NPT*18];
__device__ int    g_cand[(size_t)B*NPT*NCAND];
__device__ double g_dbuf[(size_t)B*NPT*CIN + (size_t)B*NPT];
__device__ float  g_sbuf[(size_t)B*MPT*MPT];   // materialized attention scores s[b][n][m]

// ---------------------------------------------------------------------------
// 0. Weight prep: W1AB=[Wa1;Wb1] (512x128), W2A/W2B (256x128), WFG=[Wf;Wg]
// ---------------------------------------------------------------------------
__global__ void prep_w_kernel(const float* __restrict__ Wa, const float* __restrict__ Wb,
                              const float* __restrict__ Wf, const float* __restrict__ Wg,
                              float* W1AB, float* W2A, float* W2B, float* WFG) {
    int idx = blockIdx.x * 256 + threadIdx.x;
    if (idx < 65536) {
        int o = idx >> 7, c = idx & 127;
        W1AB[idx] = (o < 256) ? Wa[o*256 + c] : Wb[(o-256)*256 + c];
    } else if (idx < 98304) {
        int j = idx - 65536; int o = j >> 7, c = j & 127;
        W2A[j] = Wa[o*256 + 128 + c];
    } else if (idx < 131072) {
        int j = idx - 98304; int o = j >> 7, c = j & 127;
        W2B[j] = Wb[o*256 + 128 + c];
    } else if (idx < 131072 + 64*130) {
        int j = idx - 131072;
        WFG[j] = (j < 32*130) ? Wf[j] : Wg[j - 32*130];
    }
}

// ---------------------------------------------------------------------------
// 1. Normalize in DOUBLE, warp-per-point
// ---------------------------------------------------------------------------
__global__ __launch_bounds__(256)
void normalize_kernel(const float* __restrict__ x,
                      float* __restrict__ xn, float* __restrict__ xnT,
                      float* __restrict__ xTr, float* __restrict__ sq,
                      double* __restrict__ xnd, double* __restrict__ sqd) {
    int gw = (blockIdx.x * 256 + threadIdx.x) >> 5;
    if (gw >= B * NPT) return;
    int lane = threadIdx.x & 31;
    int b = gw >> 10, n = gw & 1023;
    const float* xp = x + (size_t)b * CIN * NPT + n;
    float vf[4];
    double ss = 0.0;
    #pragma unroll
    for (int i = 0; i < 4; i++) {
        float v = xp[(size_t)(i*32 + lane) * NPT];
        vf[i] = v;
        ss += (double)v * (double)v;
    }
    #pragma unroll
    for (int off = 16; off > 0; off >>= 1)
        ss += __shfl_xor_sync(0xffffffffu, ss, off);
    double nrm = sqrt(ss); if (nrm < 1e-12) nrm = 1e-12;
    double inv = 1.0 / nrm;
    double s2 = 0.0;
    #pragma unroll
    for (int i = 0; i < 4; i++) {
        int c = i*32 + lane;
        double v = (double)vf[i] * inv;
        xn[((size_t)b*CIN + c) * NPT + n] = (float)v;
        xnT[((size_t)b*NPT + n) * CIN + c] = (float)v;
        xTr[((size_t)b*NPT + n) * CIN + c] = vf[i];
        xnd[((size_t)b*NPT + n) * CIN + c] = v;
        s2 += v * v;
    }
    #pragma unroll
    for (int off = 16; off > 0; off >>= 1)
        s2 += __shfl_xor_sync(0xffffffffu, s2, off);
    if (lane == 0) { sq[gw] = (float)s2; sqd[gw] = s2; }
}

// ---------------------------------------------------------------------------
// 2. Tiled GEMM v2: 64x64 block, 4m x 4n per thread
// ---------------------------------------------------------------------------
__global__ __launch_bounds__(256)
void gemm_kernel(const float* __restrict__ A, size_t aStride,
                 const float* __restrict__ X, const float* __restrict__ bias,
                 float* __restrict__ C, int M, int K, int Nn, int doRelu) {
    __shared__ float As[32][68];   // [k][m]
    __shared__ float Xs[32][68];   // [k][n]
    int b = blockIdx.z;
    const float* Ab = A + (size_t)b * aStride;
    const float* Xb = X + (size_t)b * K * Nn;
    float* Cb = C + (size_t)b * M * Nn;
    int m0 = blockIdx.y * 64, n0 = blockIdx.x * 64;
    int tid = threadIdx.x;
    int tn = tid & 15, tm = tid >> 4;
    u64 acc[4][2] = {};
    int kTiles = (K + 31) / 32;
    for (int kt = 0; kt < kTiles; kt++) {
        int k0 = kt * 32;
        for (int i = tid; i < 64*32; i += 256) {
            int m = i >> 5, k = i & 31;
            float v = 0.f;
            if (m0 + m < M && k0 + k < K) v = Ab[(size_t)(m0+m)*K + k0 + k];
            As[k][m] = v;
        }
        for (int i = tid; i < 32*64; i += 256) {
            int k = i >> 6, n = i & 63;
            float v = 0.f;
            if (k0 + k < K) v = Xb[(size_t)(k0+k)*Nn + n0 + n];
            Xs[k][n] = v;
        }
        __syncthreads();
        #pragma unroll
        for (int kk = 0; kk < 32; kk++) {
            float4 a4 = *reinterpret_cast<const float4*>(&As[kk][tm*4]);
            u64 x0 = *reinterpret_cast<const u64*>(&Xs[kk][tn*4]);
            u64 x1 = *reinterpret_cast<const u64*>(&Xs[kk][tn*4 + 2]);
            u64 a0 = dup2(a4.x), a1 = dup2(a4.y), a2 = dup2(a4.z), a3 = dup2(a4.w);
            acc[0][0] = fma2(a0, x0, acc[0][0]); acc[0][1] = fma2(a0, x1, acc[0][1]);
            acc[1][0] = fma2(a1, x0, acc[1][0]); acc[1][1] = fma2(a1, x1, acc[1][1]);
            acc[2][0] = fma2(a2, x0, acc[2][0]); acc[2][1] = fma2(a2, x1, acc[2][1]);
            acc[3][0] = fma2(a3, x0, acc[3][0]); acc[3][1] = fma2(a3, x1, acc[3][1]);
        }
        __syncthreads();
    }
    #pragma unroll
    for (int mi = 0; mi < 4; mi++) {
        int m = m0 + tm*4 + mi;
        if (m >= M) continue;
        float bv = bias ? bias[m] : 0.f;
        float4 o4;
        unpack2(acc[mi][0], o4.x, o4.y);
        unpack2(acc[mi][1], o4.z, o4.w);
        o4.x += bv; o4.y += bv; o4.z += bv; o4.w += bv;
        if (doRelu) {
            o4.x = fmaxf(o4.x, 0.f); o4.y = fmaxf(o4.y, 0.f);
            o4.z = fmaxf(o4.z, 0.f); o4.w = fmaxf(o4.w, 0.f);
        }
        *reinterpret_cast<float4*>(&Cb[(size_t)m*Nn + n0 + tn*4]) = o4;
    }
}

// ---------------------------------------------------------------------------
// 3a. Candidate top-24, warp-per-row
// ---------------------------------------------------------------------------
__global__ __launch_bounds__(256)
void topk_cand_kernel(const float* __restrict__ dot, const float* __restrict__ sq,
                      int* __restrict__ candout) {
    int warp = threadIdx.x >> 5, lane = threadIdx.x & 31;
    int bn = blockIdx.x * 8 + warp;
    int b = bn >> 10;
    const float* drow = dot + (size_t)bn * 1024;
    const float* sqb = sq + b * 1024;
    float sqn = sqb[bn & 1023];
    float val[32];
    #pragma unroll
    for (int q = 0; q < 32; q++) {
        int m = q * 32 + lane;
        float t1 = __fadd_rn(sqn, -__fmul_rn(2.f, drow[m]));
        val[q] = -__fadd_rn(t1, sqb[m]);
    }
    float bv = val[0]; int bq = 0;
    #pragma unroll
    for (int q = 1; q < 32; q++) if (val[q] > bv) { bv = val[q]; bq = q; }
    for (int it = 0; it < NCAND; it++) {
        float v = bv; int bi = bq * 32 + lane;
        #pragma unroll
        for (int off = 16; off > 0; off >>= 1) {
            float v2 = __shfl_xor_sync(0xffffffffu, v, off);
            int   i2 = __shfl_xor_sync(0xffffffffu, bi, off);
            if (v2 > v || (v2 == v && i2 < bi)) { v = v2; bi = i2; }
        }
        if (lane == 0) candout[(size_t)bn*NCAND + it] = bi;
        if ((bi & 31) == lane) {
            int qs = bi >> 5;
            #pragma unroll
            for (int q = 0; q < 32; q++) if (q == qs) val[q] = -INFINITY;
            bv = val[0]; bq = 0;
            #pragma unroll
            for (int q = 1; q < 32; q++) if (val[q] > bv) { bv = val[q]; bq = q; }
        }
    }
}

// ---------------------------------------------------------------------------
// 3b. Refine: exact double dists, fp32-round, stable sort, top-18
// ---------------------------------------------------------------------------
__global__ __launch_bounds__(128)
void refine_topk_kernel(const double* __restrict__ xnd, const double* __restrict__ sqd,
                        const int* __restrict__ cand, int* __restrict__ idxout) {
    int bn = blockIdx.x;
    int b = bn >> 10;
    int tid = threadIdx.x, lane = tid & 31, warp = tid >> 5;
    __shared__ float scores[NCAND];
    __shared__ int   cidx[NCAND];
    if (tid < NCAND) cidx[tid] = cand[(size_t)bn*NCAND + tid];
    const double* xrp = xnd + (size_t)bn * 128 + lane * 4;
    double xr0 = xrp[0], xr1 = xrp[1], xr2 = xrp[2], xr3 = xrp[3];
    __syncthreads();
    double sqn = sqd[bn];
    for (int k = warp; k < NCAND; k += 4) {
        int m = cidx[k];
        const double* xm = xnd + ((size_t)b*NPT + m) * 128 + lane * 4;
        double s = xr0*xm[0] + xr1*xm[1] + xr2*xm[2] + xr3*xm[3];
        #pragma unroll
        for (int off = 16; off > 0; off >>= 1)
            s += __shfl_xor_sync(0xffffffffu, s, off);
        if (lane == 0)
            scores[k] = (float)(-(sqn - 2.0 * s + sqd[(size_t)b*NPT + m]));
    }
    __syncthreads();
    if (tid == 0) {
        float sc[NCAND]; int ci[NCAND];
        for (int i = 0; i < NCAND; i++) { sc[i] = scores[i]; ci[i] = cidx[i]; }
        for (int i = 1; i < NCAND; i++) {
            float sv = sc[i]; int iv = ci[i];
            int j = i - 1;
            while (j >= 0 && (sc[j] < sv || (sc[j] == sv && ci[j] > iv))) {
                sc[j+1] = sc[j]; ci[j+1] = ci[j]; j--;
            }
            sc[j+1] = sv; ci[j+1] = iv;
        }
        for (int r = 0; r < 18; r++) idxout[(size_t)bn*18 + r] = ci[r];
    }
}

// ---------------------------------------------------------------------------
// 4. FUSED edge conv v2: 64o x 64n block, 4x4 thread tile
// ---------------------------------------------------------------------------
__global__ __launch_bounds__(256)
void edge_fused_kernel(const float* __restrict__ W2, const float* __restrict__ u,
                       int uoff, const float* __restrict__ xT, const int* __restrict__ ibuf,
                       int step, float* __restrict__ Mx, float* __restrict__ part) {
    __shared__ float W2s[128][68];  // [k][m-64]
    __shared__ float Xs[32][68];    // [k][n]
    __shared__ int   js[64];
    int b = blockIdx.z, bx = blockIdx.x;
    int m0 = blockIdx.y * 64, n0 = bx * 64;
    int tid = threadIdx.x;
    int tn = tid & 15, tm = tid >> 4;
    const float* xTb = xT + (size_t)b * NPT * CIN;

    for (int i = tid; i < 64*128; i += 256) {
        int m = i >> 7, k = i & 127;
        W2s[k][m] = W2[(size_t)(m0+m)*128 + k];
    }
    float4 u4[4];
    #pragma unroll
    for (int mi = 0; mi < 4; mi++)
        u4[mi] = *reinterpret_cast<const float4*>(
            &u[((size_t)b*512 + uoff + m0 + tm*4 + mi)*NPT + n0 + tn*4]);

    float mx[4][4], s1[4] = {0,0,0,0}, s2s[4] = {0,0,0,0};
    #pragma unroll
    for (int mi = 0; mi < 4; mi++)
        #pragma unroll
        for (int q = 0; q < 4; q++) mx[mi][q] = -INFINITY;
    __syncthreads();

    for (int k = 0; k < 9; k++) {
        if (tid < 64) js[tid] = ibuf[((size_t)b*NPT + n0 + tid)*18 + k*step];
        u64 acc[4][2] = {};
        #pragma unroll
        for (int ct = 0; ct < 4; ct++) {
            __syncthreads();
            for (int i = tid; i < 32*64; i += 256) {
                int c = i & 31, n = i >> 5;
                float xj = xTb[(size_t)js[n]*128 + ct*32 + c];
                float xi = xTb[(size_t)(n0 + n)*128 + ct*32 + c];
                Xs[c][n] = __fadd_rn(xj, -xi);
            }
            __syncthreads();
            #pragma unroll
            for (int kk = 0; kk < 32; kk++) {
                float4 a4 = *reinterpret_cast<const float4*>(&W2s[ct*32+kk][tm*4]);
                u64 x0 = *reinterpret_cast<const u64*>(&Xs[kk][tn*4]);
                u64 x1 = *reinterpret_cast<const u64*>(&Xs[kk][tn*4 + 2]);
                u64 a0 = dup2(a4.x), a1 = dup2(a4.y), a2 = dup2(a4.z), a3 = dup2(a4.w);
                acc[0][0] = fma2(a0, x0, acc[0][0]); acc[0][1] = fma2(a0, x1, acc[0][1]);
                acc[1][0] = fma2(a1, x0, acc[1][0]); acc[1][1] = fma2(a1, x1, acc[1][1]);
                acc[2][0] = fma2(a2, x0, acc[2][0]); acc[2][1] = fma2(a2, x1, acc[2][1]);
                acc[3][0] = fma2(a3, x0, acc[3][0]); acc[3][1] = fma2(a3, x1, acc[3][1]);
            }
        }
        #pragma unroll
        for (int mi = 0; mi < 4; mi++) {
            float d0, d1, d2, d3;
            unpack2(acc[mi][0], d0, d1);
            unpack2(acc[mi][1], d2, d3);
            float z0 = u4[mi].x + d0, z1 = u4[mi].y + d1;
            float z2 = u4[mi].z + d2, z3 = u4[mi].w + d3;
            mx[mi][0] = fmaxf(mx[mi][0], z0); mx[mi][1] = fmaxf(mx[mi][1], z1);
            mx[mi][2] = fmaxf(mx[mi][2], z2); mx[mi][3] = fmaxf(mx[mi][3], z3);
            s1[mi]  += (z0 + z1) + (z2 + z3);
            s2s[mi] += (z0*z0 + z1*z1) + (z2*z2 + z3*z3);
        }
        __syncthreads();
    }
    #pragma unroll
    for (int mi = 0; mi < 4; mi++) {
        float4 o4 = make_float4(mx[mi][0], mx[mi][1], mx[mi][2], mx[mi][3]);
        *reinterpret_cast<float4*>(
            &Mx[((size_t)b*256 + m0 + tm*4 + mi)*NPT + n0 + tn*4]) = o4;
    }
    #pragma unroll
    for (int mi = 0; mi < 4; mi++) {
        float a = s1[mi], c2 = s2s[mi];
        #pragma unroll
        for (int off = 1; off < 16; off <<= 1) {
            a  += __shfl_xor_sync(0xffffffffu, a, off);
            c2 += __shfl_xor_sync(0xffffffffu, c2, off);
        }
        if (tn == 0) {
            int o = m0 + tm*4 + mi;
            int slot = b*16 + bx;
            part[((size_t)o*64 + slot)*2]     = a;
            part[((size_t)o*64 + slot)*2 + 1] = c2;
        }
    }
}

__global__ void finalize_edge_kernel(const float* __restrict__ partA, const float* __restrict__ partB,
                                     const float* __restrict__ gA, const float* __restrict__ btA,
                                     const float* __restrict__ gB, const float* __restrict__ btB,
                                     float* aA, float* cA, float* aB, float* cB) {
    int t = threadIdx.x;
    const float invCnt = 1.f / (float)(B * NPT * KNN);
    if (t < 256) {
        float s1 = 0.f, s2 = 0.f;
        for (int j = 0; j < 64; j++) { s1 += partA[((size_t)t*64 + j)*2]; s2 += partA[((size_t)t*64 + j)*2 + 1]; }
        float m = s1 * invCnt;
        float var = s2 * invCnt - m * m;
        float a = gA[t] * rsqrtf(var + EPS_BN);
        aA[t] = a; cA[t] = btA[t] - m * a;
    } else {
        int o = t - 256;
        float s1 = 0.f, s2 = 0.f;
        for (int j = 0; j < 64; j++) { s1 += partB[((size_t)o*64 + j)*2]; s2 += partB[((size_t)o*64 + j)*2 + 1]; }
        float m = s1 * invCnt;
        float var = s2 * invCnt - m * m;
        float a = gB[o] * rsqrtf(var + EPS_BN);
        aB[o] = a; cB[o] = btB[o] - m * a;
    }
}

// ---------------------------------------------------------------------------
// 6. Build net — elementwise
// ---------------------------------------------------------------------------
__global__ __launch_bounds__(256)
void build_net_kernel(const float* __restrict__ MxA, const float* __restrict__ MxB,
                      const float* __restrict__ aA, const float* __restrict__ cA,
                      const float* __restrict__ aB, const float* __restrict__ cB,
                      float* __restrict__ net) {
    size_t idx = (size_t)blockIdx.x * 256 + threadIdx.x;
    if (idx >= (size_t)B * 130 * MPT) return;
    int b = (int)(idx / (130 * MPT));
    int r = (int)(idx - (size_t)b * 130 * MPT);
    int c = r >> 12, m = r & 4095;
    float val;
    if (c < 128) {
        int n = m >> 2, j = m & 3;
        if (j < 2) {
            int o = j*128 + c;
            val = fmaxf(0.f, aA[o] * MxA[((size_t)b*256 + o)*NPT + n] + cA[o]);
        } else {
            int o = (j-2)*128 + c;
            val = fmaxf(0.f, aB[o] * MxB[((size_t)b*256 + o)*NPT + n] + cB[o]);
        }
    } else if (c == 128) {
        val = ((m >> 10) < 2) ? -0.2f : 0.2f;
    } else {
        val = ((m >> 10) & 1) ? 0.2f : -0.2f;
    }
    net[idx] = val;
}

// ---------------------------------------------------------------------------
// 7. FUSED attention BN stats (194 blocks) + fused normalize+relu
// ---------------------------------------------------------------------------
__global__ __launch_bounds__(256)
void stats_fused_kernel(const float* __restrict__ PFG, const float* __restrict__ Ph,
                        const float* __restrict__ gf, const float* __restrict__ bef,
                        const float* __restrict__ gg, const float* __restrict__ beg,
                        const float* __restrict__ gh, const float* __restrict__ beh,
                        float* __restrict__ scfg, float* __restrict__ bifg,
                        float* __restrict__ sch,  float* __restrict__ bih) {
    int bid = blockIdx.x;
    const float* base; int C, c; float gv, bev; float *scp, *bip;
    if (bid < 64) {
        base = PFG; C = 64; c = bid;
        gv  = (c < 32) ? gf[c]  : gg[c-32];
        bev = (c < 32) ? bef[c] : beg[c-32];
        scp = scfg; bip = bifg;
    } else {
        base = Ph; C = 130; c = bid - 64;
        gv = gh[c]; bev = beh[c];
        scp = sch; bip = bih;
    }
    int tid = threadIdx.x;
    float s1 = 0.f, s2 = 0.f;
    for (int b = 0; b < B; b++) {
        const float* p = base + ((size_t)b*C + c) * MPT;
        for (int m = tid; m < MPT; m += 256) { float v = p[m]; s1 += v; s2 += v*v; }
    }
    __shared__ float r1[256], r2[256];
    r1[tid] = s1; r2[tid] = s2;
    __syncthreads();
    for (int s = 128; s > 0; s >>= 1) {
        if (tid < s) { r1[tid] += r1[tid+s]; r2[tid] += r2[tid+s]; }
        __syncthreads();
    }
    if (tid == 0) {
        const float invCnt = 1.f / (float)(B * MPT);
        float m = r1[0] * invCnt;
        float var = r2[0] * invCnt - m * m;
        float a = gv * rsqrtf(var + EPS_BN);
        scp[c] = a; bip[c] = bev - m * a;
    }
}

__global__ void norm_relu_fused_kernel(const float* __restrict__ PFG, const float* __restrict__ Ph,
                                       const float* __restrict__ scfg, const float* __restrict__ bifg,
                                       const float* __restrict__ sch,  const float* __restrict__ bih,
                                       float* __restrict__ FG, float* __restrict__ HnB) {
    size_t idx = (size_t)blockIdx.x * 256 + threadIdx.x;
    size_t t1 = (size_t)B * 64 * MPT;
    size_t t2 = (size_t)B * 130 * MPT;
    if (idx < t1) {
        int c = (int)((idx / MPT) % 64);
        FG[idx] = fmaxf(0.f, PFG[idx] * scfg[c] + bifg[c]);
    } else if (idx < t1 + t2) {
        size_t j = idx - t1;
        int c = (int)((j / MPT) % 130);
        HnB[j] = fmaxf(0.f, Ph[j] * sch[c] + bih[c]);
    }
}

// ---------------------------------------------------------------------------
// 8. Attention pass 1: 16 rows/block; also MATERIALIZES s to gmem.
// ---------------------------------------------------------------------------
__global__ __launch_bounds__(256)
void att_pass1_kernel(const float* __restrict__ FG, float* __restrict__ sraw,
                      float* __restrict__ rmax, float* __restrict__ rinv) {
    int b = blockIdx.y;
    int n0 = blockIdx.x * 16;
    const float* F = FG + (size_t)b * 64 * MPT;
    const float* G = F + (size_t)32 * MPT;
    __shared__ u64 Gs2[16][17];
    __shared__ float smx[16][256];
    __shared__ float ssm[16][256];
    int tid = threadIdx.x;
    {
        int cp = tid >> 4, r = tid & 15;
        float g0 = G[(size_t)(2*cp) * MPT + n0 + r];
        float g1 = G[(size_t)(2*cp + 1) * MPT + n0 + r];
        Gs2[cp][r] = pack2(g0, g1);
    }
    __syncthreads();
    float mx[16], sm[16];
    #pragma unroll
    for (int r = 0; r < 16; r++) { mx[r] = -INFINITY; sm[r] = 0.f; }
    for (int j = 0; j < 16; j++) {
        int m = tid + j * 256;
        u64 fp2[16];
        #pragma unroll
        for (int cp = 0; cp < 16; cp++) {
            float f0 = F[(size_t)(2*cp) * MPT + m];
            float f1 = F[(size_t)(2*cp + 1) * MPT + m];
            fp2[cp] = pack2(f0, f1);
        }
        #pragma unroll
        for (int r = 0; r < 16; r++) {
            u64 sacc = 0;
            #pragma unroll
            for (int cp = 0; cp < 16; cp++) sacc = fma2(fp2[cp], Gs2[cp][r], sacc);
            float s0, s1v; unpack2(sacc, s0, s1v);
            float s = s0 + s1v;
            sraw[((size_t)(b*MPT) + n0 + r) * MPT + m] = s;
            if (s > mx[r]) { sm[r] = sm[r] * __expf(mx[r] - s) + 1.f; mx[r] = s; }
            else           { sm[r] += __expf(s - mx[r]); }
        }
    }
    #pragma unroll
    for (int r = 0; r < 16; r++) { smx[r][tid] = mx[r]; ssm[r][tid] = sm[r]; }
    __syncthreads();
    int w = tid >> 5, lane = tid & 31;
    for (int rr = w; rr < 16; rr += 8) {
        float M = -INFINITY, S = 0.f;
        for (int e = lane; e < 256; e += 32) {
            float m2 = smx[rr][e], s2 = ssm[rr][e];
            if (m2 > M) { S = S * __expf(M - m2) + s2; M = m2; }
            else        { S += s2 * __expf(m2 - M); }
        }
        #pragma unroll
        for (int o = 16; o > 0; o >>= 1) {
            float m2 = __shfl_xor_sync(0xffffffffu, M, o);
            float s2 = __shfl_xor_sync(0xffffffffu, S, o);
            if (m2 > M) { S = S * __expf(M - m2) + s2; M = m2; }
            else        { S += s2 * __expf(m2 - M); }
        }
        if (lane == 0) {
            rmax[(size_t)b*MPT + n0 + rr] = M;
            rinv[(size_t)b*MPT + n0 + rr] = __fdiv_rn(1.f, S);
        }
    }
}

// ---------------------------------------------------------------------------
// 9. Attention pass 2 v6: s is PRECOMPUTED (no F/G staging, no s recompute).
//    Per nt: stage H(+rinv) + load s tile -> exp -> es; then o-phase with
//    conflict-free LDS.128 e loads. Warp owns 17 channels, lane owns 4 m.
// ---------------------------------------------------------------------------
constexpr int P2_SMEM = 136*33*8 + 32*132*4;

__global__ __launch_bounds__(256, 1)
void att_pass2_kernel(const float* __restrict__ sraw, const float* __restrict__ Hn,
                      const float* __restrict__ rmax, const float* __restrict__ rinv,
                      const float* __restrict__ net, const float* __restrict__ gamma,
                      float* __restrict__ net2) {
    extern __shared__ char smem_raw[];
    u64*   Hs2 = reinterpret_cast<u64*>(smem_raw);       // [136][33] dup(h*rinv)
    float* es  = reinterpret_cast<float*>(Hs2 + 136*33); // [32 j][132: 128 m]

    int b = blockIdx.y;
    int m0 = blockIdx.x * 128;
    int tid = threadIdx.x;
    int w = tid >> 5, lane = tid & 31;
    int c0 = w * 17;
    // s-tile staging role: thread handles row srow (0..31), 16 cols
    int srow = tid >> 3;
    int scol = (tid & 7) * 16;

    u64 acc2[17][2];
    #pragma unroll
    for (int i = 0; i < 17; i++) { acc2[i][0] = 0; acc2[i][1] = 0; }

    for (int nt = 0; nt < 128; nt++) {
        int n0v = nt * 32;
        __syncthreads();
        // stage H (scaled by rinv), dup'd into u64 lanes
        for (int idx = tid; idx < 136*32; idx += 256) {
            int c = idx >> 5, jj = idx & 31;
            float h = 0.f;
            if (c < 130)
                h = Hn[((size_t)b*130 + c) * MPT + n0v + jj] * rinv[(size_t)b*MPT + n0v + jj];
            Hs2[c*33 + jj] = dup2(h);
        }
        // stage es = exp(s - rmax): 16 values per thread, 4x float4
        {
            float rm = rmax[(size_t)b*MPT + n0v + srow];
            const float* sp = &sraw[((size_t)(b*MPT) + n0v + srow) * MPT + m0 + scol];
            #pragma unroll
            for (int q = 0; q < 4; q++) {
                float4 sv = *reinterpret_cast<const float4*>(&sp[q*4]);
                float4 ev = make_float4(__expf(sv.x - rm), __expf(sv.y - rm),
                                        __expf(sv.z - rm), __expf(sv.w - rm));
                *reinterpret_cast<float4*>(&es[srow*132 + scol + q*4]) = ev;
            }
        }
        __syncthreads();
        // o-phase: 17 channels x 4 m per thread; e via single LDS.128
        #pragma unroll 4
        for (int j = 0; j < 32; j++) {
            float4 e4 = *reinterpret_cast<const float4*>(&es[j*132 + 4*lane]);
            u64 e01 = pack2(e4.x, e4.y);
            u64 e23 = pack2(e4.z, e4.w);
            #pragma unroll
            for (int i = 0; i < 17; i++) {
                u64 h2 = Hs2[(c0 + i)*33 + j];
                acc2[i][0] = fma2(h2, e01, acc2[i][0]);
                acc2[i][1] = fma2(h2, e23, acc2[i][1]);
            }
        }
    }
    float gm = gamma[0];
    #pragma unroll
    for (int i = 0; i < 17; i++) {
        int c = c0 + i;
        if (c >= 130) break;
        size_t off = ((size_t)b*130 + c) * MPT + m0 + 4*lane;
        float a0, a1, a2, a3;
        unpack2(acc2[i][0], a0, a1);
        unpack2(acc2[i][1], a2, a3);
        float4 nv = *reinterpret_cast<const float4*>(&net[off]);
        float4 o4 = make_float4(gm*a0 + nv.x, gm*a1 + nv.y, gm*a2 + nv.z, gm*a3 + nv.w);
        *reinterpret_cast<float4*>(&net2[off]) = o4;
    }
}

// ---------------------------------------------------------------------------
// Host launch
// ---------------------------------------------------------------------------
extern "C" void kernel_launch(void* const* d_in, const int* in_sizes, int n_in,
                              void* d_out, int out_size) {
    float* buf = nullptr; int* ibuf = nullptr; int* candb = nullptr; double* dbuf = nullptr;
    float* sbuf = nullptr;
    cudaGetSymbolAddress((void**)&buf,   g_buf);
    cudaGetSymbolAddress((void**)&ibuf,  g_ibuf);
    cudaGetSymbolAddress((void**)&candb, g_cand);
    cudaGetSymbolAddress((void**)&dbuf,  g_dbuf);
    cudaGetSymbolAddress((void**)&sbuf,  g_sbuf);
    cudaFuncSetAttribute(att_pass2_kernel, cudaFuncAttributeMaxDynamicSharedMemorySize, P2_SMEM);

    const float* inp  = (const float*)d_in[0];
    const float* Wa   = (const float*)d_in[1];
    const float* gna  = (const float*)d_in[2];
    const float* bta  = (const float*)d_in[3];
    const float* Wb   = (const float*)d_in[4];
    const float* gnb  = (const float*)d_in[5];
    const float* btb  = (const float*)d_in[6];
    const float* Wf   = (const float*)d_in[7];
    const float* gf   = (const float*)d_in[9];
    const float* bef  = (const float*)d_in[10];
    const float* Wg   = (const float*)d_in[11];
    const float* gg   = (const float*)d_in[13];
    const float* beg  = (const float*)d_in[14];
    const float* Wh   = (const float*)d_in[15];
    const float* gh   = (const float*)d_in[17];
    const float* beh  = (const float*)d_in[18];
    const float* gamma= (const float*)d_in[19];
    const float* W1   = (const float*)d_in[20];
    const float* b1   = (const float*)d_in[21];
    const float* W2   = (const float*)d_in[22];
    const float* b2   = (const float*)d_in[23];
    float* out = (float*)d_out;

    float *xn   = buf + O_XN,   *xnT  = buf + O_XNT, *xTr = buf + O_XTR, *sq = buf + O_SQ;
    float *dot  = buf + O_DOT;
    float *W1AB = buf + O_W1AB, *W2A  = buf + O_W2A, *W2B = buf + O_W2B, *WFG = buf + O_WFG;
    float *U    = buf + O_U;
    float *MxA  = buf + O_MXA,  *MxB  = buf + O_MXB;
    float *partA= buf + O_PARTA,*partB= buf + O_PARTB;
    float *aA   = buf + O_AA,   *cA   = buf + O_CA,  *aB  = buf + O_AB2, *cB = buf + O_CB2;
    float *net  = buf + O_NET;
    float *PFG  = buf + O_PFG,  *Ph   = buf + O_PH;
    float *FG   = buf + O_FG,   *HnB  = buf + O_HN;
    float *scfg = buf + O_SCFG, *bifg = buf + O_BIFG;
    float *sch  = buf + O_SCH,  *bih  = buf + O_BIH;
    float *rmax = buf + O_RMAX, *rinv = buf + O_RINV;
    float *net2 = buf + O_NET2, *y1   = buf + O_Y1;
    double *xnd = dbuf;
    double *sqd = dbuf + (size_t)B*NPT*CIN;

    prep_w_kernel<<<545, 256>>>(Wa, Wb, Wf, Wg, W1AB, W2A, W2B, WFG);
    normalize_kernel<<<(B*NPT*32)/256, 256>>>(inp, xn, xnT, xTr, sq, xnd, sqd);
    gemm_kernel<<<dim3(NPT/64, 8, B), 256>>>(W1AB, 0, inp, nullptr, U, 512, CIN, NPT, 0);
    gemm_kernel<<<dim3(NPT/64, NPT/64, B), 256>>>(xnT, (size_t)NPT*CIN, xn, nullptr, dot, NPT, CIN, NPT, 0);
    topk_cand_kernel<<<(B*NPT)/8, 256>>>(dot, sq, candb);
    refine_topk_kernel<<<B*NPT, 128>>>(xnd, sqd, candb, ibuf);
    edge_fused_kernel<<<dim3(16, 4, B), 256>>>(W2A, U, 0,   xTr, ibuf, 1, MxA, partA);
    edge_fused_kernel<<<dim3(16, 4, B), 256>>>(W2B, U, 256, xTr, ibuf, 2, MxB, partB);
    finalize_edge_kernel<<<1, 512>>>(partA, partB, gna, bta, gnb, btb, aA, cA, aB, cB);
    build_net_kernel<<<(unsigned)(((size_t)B*130*MPT + 255)/256), 256>>>(MxA, MxB, aA, cA, aB, cB, net);
    gemm_kernel<<<dim3(MPT/64, 1, B), 256>>>(WFG, 0, net, nullptr, PFG, 64, 130, MPT, 0);
    gemm_kernel<<<dim3(MPT/64, 3, B), 256>>>(Wh, 0, net, nullptr, Ph, 130, 130, MPT, 0);
    stats_fused_kernel<<<194, 256>>>(PFG, Ph, gf, bef, gg, beg, gh, beh, scfg, bifg, sch, bih);
    {
        size_t tot = (size_t)B*64*MPT + (size_t)B*130*MPT;
        norm_relu_fused_kernel<<<(unsigned)((tot + 255)/256), 256>>>(PFG, Ph, scfg, bifg, sch, bih, FG, HnB);
    }
    att_pass1_kernel<<<dim3(MPT/16, B), 256>>>(FG, sbuf, rmax, rinv);
    att_pass2_kernel<<<dim3(MPT/128, B), 256, P2_SMEM>>>(sbuf, HnB, rmax, rinv, net, gamma, net2);
    gemm_kernel<<<dim3(MPT/64, 4, B), 256>>>(W1, 0, net2, b1, y1, 256, 130, MPT, 1);
    gemm_kernel<<<dim3(MPT/64, 2, B), 256>>>(W2, 0, y1, b2, out, 128, 256, MPT, 1);
}